// round 14
// baseline (speedup 1.0000x reference)
#include <cuda_runtime.h>
#include <cuda_fp16.h>
#include <math.h>
#include <stdint.h>

// Problem sizes (fixed by the reference)
#define BSZ 2048
#define GG  64
#define DD  512
#define DD2 (DD * DD)
#define NB  32
#define PNL 64

// ---------------------------------------------------------------------------
// Scratch (device globals)
// g_L : per-gaussian Cholesky factor L, COLUMN-major (i>=j at j*DD+i).
//       Row-major view is U = L^T (valid at a*DD+b, b>=a).
// g_Wt*: transposed fp16-split inverse: Wt[n][k] = V[k][n], V = U^{-1}.
// g_Xh : X rounded to fp16 (GEMM computes dist of the rounded x exactly).
// ---------------------------------------------------------------------------
__device__ __align__(16) float g_L[GG * DD2];
__device__ __align__(16) float g_Dinv[GG * 16 * NB * NB];
__device__ __align__(16) float g_u[GG * DD];
__device__ __align__(16) float g_dist[BSZ * GG];
__device__ __align__(16) __half g_Xh[BSZ * DD];
__device__ __align__(16) __half g_Wthi[GG * DD2];
__device__ __align__(16) __half g_Wtlo[GG * DD2];

#define CLUSTER_SYNC() do { \
    asm volatile("barrier.cluster.arrive.aligned;" ::: "memory"); \
    asm volatile("barrier.cluster.wait.aligned;"   ::: "memory"); \
} while (0)

// ---------------------------------------------------------------------------
// mma.sync / cp.async helpers (portable sm_80+ path)
// ---------------------------------------------------------------------------
__device__ __forceinline__ void ldmx4(uint32_t* r, uint32_t addr) {
    asm volatile("ldmatrix.sync.aligned.m8n8.x4.shared.b16 {%0,%1,%2,%3}, [%4];"
                 : "=r"(r[0]), "=r"(r[1]), "=r"(r[2]), "=r"(r[3]) : "r"(addr));
}
__device__ __forceinline__ void mma16816h(float* d, const uint32_t* a, const uint32_t* b) {
    asm volatile(
        "mma.sync.aligned.m16n8k16.row.col.f32.f16.f16.f32 "
        "{%0,%1,%2,%3}, {%4,%5,%6,%7}, {%8,%9}, {%0,%1,%2,%3};"
        : "+f"(d[0]), "+f"(d[1]), "+f"(d[2]), "+f"(d[3])
        : "r"(a[0]), "r"(a[1]), "r"(a[2]), "r"(a[3]), "r"(b[0]), "r"(b[1]));
}
__device__ __forceinline__ void cp16(uint32_t s, const void* g) {
    asm volatile("cp.async.ca.shared.global [%0], [%1], 16;" :: "r"(s), "l"(g));
}

// ---------------------------------------------------------------------------
// Warp-level 32x32 Cholesky in REGISTERS (lane = row, shfl column broadcast).
// ---------------------------------------------------------------------------
__device__ __forceinline__ void warp_chol32(float (*s)[PNL + 1], int roff, int coff,
                                            float* rdiag)
{
    const int lane = threadIdx.x;   // caller guarantees tid < 32
    float x[32];
    #pragma unroll
    for (int j = 0; j < 32; ++j) x[j] = s[roff + lane][coff + j];

    float myrs = 0.f;
    #pragma unroll
    for (int k = 0; k < 32; ++k) {
        float dval = __shfl_sync(0xffffffffu, x[k], k);
        float rs = rsqrtf(dval);
        if (lane == k) { x[k] = dval * rs; myrs = rs; }
        float lik = (lane > k) ? x[k] * rs : 0.f;
        if (lane > k) x[k] = lik;
        #pragma unroll
        for (int j = k + 1; j < 32; ++j) {
            float ljk = __shfl_sync(0xffffffffu, lik, j);
            x[j] -= lik * ljk;
        }
    }
    #pragma unroll
    for (int j = 0; j < 32; ++j) s[roff + lane][coff + j] = x[j];
    rdiag[roff + lane] = myrs;
}

// ---------------------------------------------------------------------------
// Kernel 1: fused blocked Cholesky (unchanged from R13 WIN state).
// ---------------------------------------------------------------------------
#define CHOL_SMEM ((64*65 + 64 + 3*64*68) * 4)

__global__ __launch_bounds__(512) __cluster_dims__(2, 1, 1)
void chol_fused(const float* __restrict__ covs)
{
    extern __shared__ float smc[];
    float (*s11)[PNL + 1] = (float(*)[PNL + 1])smc;
    float* rdiag          = smc + 64 * 65;
    float (*Pi)[68]       = (float(*)[68])(smc + 64 * 65 + 64);
    float (*Pj0)[68]      = (float(*)[68])(smc + 64 * 65 + 64 + 64 * 68);
    float (*Pj1)[68]      = (float(*)[68])(smc + 64 * 65 + 64 + 2 * 64 * 68);

    const int g = blockIdx.x >> 1;
    unsigned crank;
    asm("mov.u32 %0, %%cluster_ctarank;" : "=r"(crank));
    float* a = g_L + (size_t)g * DD2;
    const float* cv = covs + (size_t)g * DD2;
    const int tid = threadIdx.x;

    const uint32_t sPi  = (uint32_t)__cvta_generic_to_shared(&Pi[0][0]);
    const uint32_t sPj0 = (uint32_t)__cvta_generic_to_shared(&Pj0[0][0]);
    const uint32_t sPj1 = (uint32_t)__cvta_generic_to_shared(&Pj1[0][0]);

    for (int p = 0; p < DD / PNL; ++p) {
        const int base = p * PNL;
        const int r = DD - base - PNL;
        const float* src = (p == 0) ? cv : a;

        for (int q = tid; q < PNL * PNL; q += 512) {
            int i = q & 63, j = q >> 6;
            s11[i][j] = src[(size_t)(base + j) * DD + (base + i)];
        }
        __syncthreads();

        if (tid < 32) warp_chol32(s11, 0, 0, rdiag);
        __syncthreads();

        if (tid < 32) {
            const int row = 32 + tid;
            float x[32];
            #pragma unroll
            for (int j = 0; j < 32; ++j) x[j] = s11[row][j];
            #pragma unroll
            for (int j = 0; j < 32; ++j) {
                float s = x[j];
                #pragma unroll
                for (int k = 0; k < j; ++k)
                    s -= x[k] * s11[j][k];
                x[j] = s * rdiag[j];
            }
            #pragma unroll
            for (int j = 0; j < 32; ++j) s11[row][j] = x[j];
        }
        __syncthreads();

        #pragma unroll
        for (int e = 0; e < 2; ++e) {
            const int idx = tid + e * 512;
            const int i2 = 32 + (idx >> 5);
            const int j2 = 32 + (idx & 31);
            float s = 0.f;
            #pragma unroll
            for (int k = 0; k < 32; ++k)
                s += s11[i2][k] * s11[j2][k];
            s11[i2][j2] -= s;
        }
        __syncthreads();

        if (tid < 32) warp_chol32(s11, 32, 32, rdiag);
        __syncthreads();

        if (crank == 0) {
            for (int q = tid; q < PNL * PNL; q += 512) {
                int i = q & 63, j = q >> 6;
                if (i >= j) a[(size_t)(base + j) * DD + (base + i)] = s11[i][j];
            }
        }

        if (r > 0) {
            const int chunk = r >> 1;
            const int row = (int)crank * chunk + tid;
            if (row < r && tid < chunk) {
                const int gr = base + PNL + row;
                float x[PNL];
                #pragma unroll
                for (int j = 0; j < PNL; ++j)
                    x[j] = src[(size_t)(base + j) * DD + gr];
                #pragma unroll
                for (int j = 0; j < PNL; ++j) {
                    float s = x[j];
                    #pragma unroll
                    for (int k = 0; k < j; ++k)
                        s -= x[k] * s11[j][k];
                    x[j] = s * rdiag[j];
                }
                #pragma unroll
                for (int j = 0; j < PNL; ++j)
                    a[(size_t)(base + j) * DD + gr] = x[j];
            }
        }
        CLUSTER_SYNC();

        if (r > 0) {
            const int m = r >> 6;
            for (int ti = (int)crank; ti < m; ti += 2) {
                const int gi = ti * 64;

                #pragma unroll
                for (int e = 0; e < 2; ++e) {
                    const int f = tid * 2 + e;
                    const int col = f >> 4, r4 = f & 15;
                    cp16(sPi + (uint32_t)((col * 68 + r4 * 4) * 4),
                         a + (size_t)(base + col) * DD + base + PNL + gi + r4 * 4);
                }
                if (ti > 0) {
                    #pragma unroll
                    for (int e = 0; e < 2; ++e) {
                        const int f = tid * 2 + e;
                        const int col = f >> 4, r4 = f & 15;
                        cp16(sPj0 + (uint32_t)((col * 68 + r4 * 4) * 4),
                             a + (size_t)(base + col) * DD + base + PNL + r4 * 4);
                    }
                }
                asm volatile("cp.async.commit_group;");
                asm volatile("cp.async.wait_group 0;");
                __syncthreads();

                for (int tj = 0; tj <= ti; ++tj) {
                    if (tj + 1 < ti) {
                        const int gjn = (tj + 1) * 64;
                        const uint32_t dstb = ((tj + 1) & 1) ? sPj1 : sPj0;
                        #pragma unroll
                        for (int e = 0; e < 2; ++e) {
                            const int f = tid * 2 + e;
                            const int col = f >> 4, r4 = f & 15;
                            cp16(dstb + (uint32_t)((col * 68 + r4 * 4) * 4),
                                 a + (size_t)(base + col) * DD + base + PNL + gjn + r4 * 4);
                        }
                        asm volatile("cp.async.commit_group;");
                    }

                    const int gj = tj * 64;
                    const float (*PJ)[68] = (tj == ti) ? Pi
                                           : ((tj & 1) ? Pj1 : Pj0);
                    const int tx = tid & 15;
                    const int ty = tid >> 4;
                    float acc[4][2];
                    #pragma unroll
                    for (int ii = 0; ii < 4; ++ii) { acc[ii][0] = 0.f; acc[ii][1] = 0.f; }

                    #pragma unroll
                    for (int k = 0; k < PNL; ++k) {
                        float4 pi = *(const float4*)&Pi[k][tx * 4];
                        float2 pj = *(const float2*)&PJ[k][ty * 2];
                        float pr[4] = {pi.x, pi.y, pi.z, pi.w};
                        #pragma unroll
                        for (int ii = 0; ii < 4; ++ii) {
                            acc[ii][0] += pr[ii] * pj.x;
                            acc[ii][1] += pr[ii] * pj.y;
                        }
                    }

                    const int rowb = gi + tx * 4;
                    #pragma unroll
                    for (int jj = 0; jj < 2; ++jj) {
                        const int colg = gj + ty * 2 + jj;
                        const size_t off = (size_t)(base + PNL + colg) * DD + base + PNL + rowb;
                        float4 cvv = *(const float4*)(src + off);
                        cvv.x -= acc[0][jj]; cvv.y -= acc[1][jj];
                        cvv.z -= acc[2][jj]; cvv.w -= acc[3][jj];
                        *(float4*)(a + off) = cvv;
                    }

                    if (tj + 1 < ti) {
                        asm volatile("cp.async.wait_group 0;");
                        __syncthreads();
                    }
                }
            }
        }
        CLUSTER_SYNC();
    }
}

// ---------------------------------------------------------------------------
// Kernel 2a: invert 16 diagonal 32x32 blocks of U = L^T (one warp per (g,d))
// + fused X->fp16 conversion slice (absorbs the old split_x launch).
// ---------------------------------------------------------------------------
__global__ __launch_bounds__(128, 8)
void diaginv_split_kernel(const float* __restrict__ X)
{
    __shared__ float su[4][NB][NB + 1];
    __shared__ float sx[4][NB][NB + 1];

    const int g = blockIdx.x;
    const int w = threadIdx.x >> 5;
    const int d = blockIdx.y * 4 + w;
    const int cc = threadIdx.x & 31;
    const float* U = g_L + (size_t)g * DD2;
    const int b0 = d * NB;

    // fused split_x slice: 256 blocks x 1024 float4
    {
        const int blk = blockIdx.y * GG + blockIdx.x;   // 0..255
        const int base = blk * 1024 + threadIdx.x;
        #pragma unroll
        for (int e = 0; e < 8; ++e) {
            const int i = base + e * 128;
            float4 v = ((const float4*)X)[i];
            __half h[4] = {__float2half(v.x), __float2half(v.y),
                           __float2half(v.z), __float2half(v.w)};
            ((uint2*)g_Xh)[i] = *(uint2*)h;
        }
    }

    for (int rr = 0; rr < NB; ++rr)
        su[w][rr][cc] = U[(size_t)(b0 + rr) * DD + (b0 + cc)];
    __syncwarp();

    for (int t = cc; t >= 0; --t) {
        float s = (t == cc) ? 1.f : 0.f;
        for (int ss = t + 1; ss <= cc; ++ss)
            s -= su[w][t][ss] * sx[w][ss][cc];
        sx[w][t][cc] = s / su[w][t][t];
    }
    __syncwarp();

    float* dst = g_Dinv + ((size_t)g * 16 + d) * NB * NB;
    for (int t = 0; t < NB; ++t)
        dst[t * NB + cc] = (t <= cc) ? sx[w][t][cc] : 0.f;
}

// ---------------------------------------------------------------------------
// Kernel 2b: blocked triangular inverse + fused u + fused transposed fp16
// split output. One CTA per (g, block-column j), largest j first.
// v2: 128 threads, 8 rows/thread (warp q -> rows q*8..q*8+7, lane = col).
// Raises FMA:smem-wavefront ratio from 16:8 to 32:12 -> FMA-bound.
// Summation order per entry identical to the measured-good R11 kernel.
// ---------------------------------------------------------------------------
#define T2_SMEM ((512*36 + 4*32*36 + 32*33 + 4*36) * 4)

__global__ __launch_bounds__(128)
void trinv_col_kernel(const float* __restrict__ mus)
{
    extern __shared__ float sm2[];
    float (*Vs)[36]     = (float(*)[36])sm2;
    float (*Us)[32][36] = (float(*)[32][36])(sm2 + 512 * 36);
    float (*Ts)[33]     = (float(*)[33])(sm2 + 512 * 36 + 4 * 32 * 36);
    float (*red)[36]    = (float(*)[36])(sm2 + 512 * 36 + 4 * 32 * 36 + 32 * 33);

    const int g = blockIdx.x;
    const int j = 15 - blockIdx.y;          // largest columns first
    const float* U = g_L + (size_t)g * DD2;
    const int tid = threadIdx.x;
    const int cc  = tid & 31;
    const int q   = tid >> 5;               // warp 0..3 -> rows q*8..q*8+7

    // diag block: V[j][j] = Dinv[j]
    {
        const float* din = g_Dinv + ((size_t)g * 16 + j) * NB * NB;
        #pragma unroll
        for (int r8 = 0; r8 < 8; ++r8) {
            const int t = q * 8 + r8;
            Vs[j * NB + t][cc] = din[t * NB + cc];
        }
    }
    __syncthreads();

    for (int i = j - 1; i >= 0; --i) {
        float acc[8];
        #pragma unroll
        for (int r8 = 0; r8 < 8; ++r8) acc[r8] = 0.f;

        for (int kc = i + 1; kc <= j; kc += 4) {
            const int nk = (j - kc + 1 < 4) ? (j - kc + 1) : 4;
            // stage nk U blocks: nk*256 float4, 128 threads
            #pragma unroll
            for (int e = 0; e < 8; ++e) {
                const int f = tid + 128 * e;        // 0..1023
                const int b = f >> 8;
                if (b < nk) {
                    const int rem = f & 255, rr = rem >> 3, t4 = rem & 7;
                    *(float4*)&Us[b][rr][t4 * 4] =
                        *(const float4*)&U[(size_t)(i * NB + rr) * DD + (kc + b) * NB + t4 * 4];
                }
            }
            __syncthreads();
            for (int b = 0; b < nk; ++b) {
                const int k = kc + b;
                #pragma unroll
                for (int t4 = 0; t4 < 8; ++t4) {
                    float v0 = Vs[k * NB + t4 * 4 + 0][cc];
                    float v1 = Vs[k * NB + t4 * 4 + 1][cc];
                    float v2 = Vs[k * NB + t4 * 4 + 2][cc];
                    float v3 = Vs[k * NB + t4 * 4 + 3][cc];
                    #pragma unroll
                    for (int r8 = 0; r8 < 8; ++r8) {
                        float4 u4 = *(const float4*)&Us[b][q * 8 + r8][t4 * 4];
                        acc[r8] += u4.x * v0 + u4.y * v1 + u4.z * v2 + u4.w * v3;
                    }
                }
            }
            __syncthreads();
        }

        // Ts = T; stage Dinv[i]; V[i][j] = -Dinv[ii] * T
        #pragma unroll
        for (int r8 = 0; r8 < 8; ++r8) Ts[q * 8 + r8][cc] = acc[r8];
        #pragma unroll
        for (int e = 0; e < 2; ++e) {
            const int f = tid + 128 * e;            // 0..255
            const int rr = f >> 3, t4 = f & 7;
            *(float4*)&Us[0][rr][t4 * 4] =
                *(const float4*)&g_Dinv[((size_t)g * 16 + i) * NB * NB + rr * NB + t4 * 4];
        }
        __syncthreads();

        float acc2[8];
        #pragma unroll
        for (int r8 = 0; r8 < 8; ++r8) acc2[r8] = 0.f;
        #pragma unroll
        for (int t4 = 0; t4 < 8; ++t4) {
            float v0 = Ts[t4 * 4 + 0][cc];
            float v1 = Ts[t4 * 4 + 1][cc];
            float v2 = Ts[t4 * 4 + 2][cc];
            float v3 = Ts[t4 * 4 + 3][cc];
            #pragma unroll
            for (int r8 = 0; r8 < 8; ++r8) {
                float4 u4 = *(const float4*)&Us[0][q * 8 + r8][t4 * 4];
                acc2[r8] += u4.x * v0 + u4.y * v1 + u4.z * v2 + u4.w * v3;
            }
        }
        #pragma unroll
        for (int r8 = 0; r8 < 8; ++r8)
            Vs[i * NB + q * 8 + r8][cc] = -acc2[r8];
        __syncthreads();
    }

    // fused output: Wt[n][k] = V[k][n], fp16 hi/lo, zero-padded to 128-tile
    {
        __half* Whi = g_Wthi + (size_t)g * DD2;
        __half* Wlo = g_Wtlo + (size_t)g * DD2;
        const int kmax  = (j + 1) * NB;
        const int kfill = 128 * ((j >> 2) + 1);
        for (int nl = q; nl < NB; nl += 4) {
            const size_t nbase = (size_t)(j * NB + nl) * DD;
            for (int k = cc; k < kmax; k += 32) {
                float f = Vs[k][nl];
                __half h = __float2half(f);
                __half l = __float2half(f - __half2float(h));
                Whi[nbase + k] = h;
                Wlo[nbase + k] = l;
            }
            for (int k = kmax + cc; k < kfill; k += 32) {
                Whi[nbase + k] = __float2half(0.f);
                Wlo[nbase + k] = __float2half(0.f);
            }
        }
    }

    // fused u
    {
        const float* mu = mus + (size_t)g * DD;
        float s = 0.f;
        for (int row = q; row < (j + 1) * NB; row += 4)
            s += mu[row] * Vs[row][cc];
        red[q][cc] = s;
        __syncthreads();
        if (q == 0) {
            float tot = 0.f;
            #pragma unroll
            for (int w4 = 0; w4 < 4; ++w4) tot += red[w4][cc];
            g_u[(size_t)g * DD + j * NB + cc] = tot;
        }
    }
}

// ---------------------------------------------------------------------------
// Kernel 4: fp16 2-product GEMM via mma.sync + fused dist epilogue.
// (unchanged from R13 WIN state)
// ---------------------------------------------------------------------------
#define PITCH_A 24
#define PITCH_B 40

__global__ __launch_bounds__(256, 2)
void mma_dist_kernel()
{
    __shared__ __align__(16) __half As[2][128][PITCH_A];
    __shared__ __align__(16) __half Bs[2][128][PITCH_B];
    __shared__ float sU[512];
    __shared__ float red[128][4];

    const int tid  = threadIdx.x;
    const int lane = tid & 31;
    const int wid  = tid >> 5;
    const int wm   = wid & 1;
    const int wn   = wid >> 1;
    const int g    = blockIdx.y;
    const int b0   = blockIdx.x * 128;

    for (int c = tid; c < 512; c += 256) sU[c] = g_u[(size_t)g * DD + c];

    const __half* Xh = g_Xh + (size_t)b0 * DD;
    const __half* Wh = g_Wthi + (size_t)g * DD2;
    const __half* Wl = g_Wtlo + (size_t)g * DD2;

    const uint32_t aS = (uint32_t)__cvta_generic_to_shared(&As[0][0][0]);
    const uint32_t bS = (uint32_t)__cvta_generic_to_shared(&Bs[0][0][0]);
    const uint32_t BUFA = 128 * PITCH_A * 2;
    const uint32_t BUFB = 128 * PITCH_B * 2;

    const int lrow = tid >> 1;
    const int hsel = tid & 1;
    const int brow = ((lane >> 4) << 3) + (lane & 7);
    const int bcol = ((lane >> 3) & 1) * 8;

    float distacc[8];
    #pragma unroll
    for (int i = 0; i < 8; ++i) distacc[i] = 0.f;

    for (int nt = 0; nt < 4; ++nt) {
        const int n0 = nt * 128;
        const int nsteps = (nt + 1) * 8;
        const int sbound = nt * 8 + 2 * wn + 2;

        float acc[4][4][4];
        #pragma unroll
        for (int mt = 0; mt < 4; ++mt)
            #pragma unroll
            for (int jc = 0; jc < 4; ++jc)
                #pragma unroll
                for (int e = 0; e < 4; ++e) acc[mt][jc][e] = 0.f;

        {
            cp16(aS + lrow * (PITCH_A * 2) + hsel * 16,
                 Xh + (size_t)lrow * DD + hsel * 8);
            const uint32_t br = bS + lrow * (PITCH_B * 2);
            const __half* wh = Wh + (size_t)(n0 + lrow) * DD;
            const __half* wl = Wl + (size_t)(n0 + lrow) * DD;
            cp16(br + hsel * 16, wh + hsel * 8);
            cp16(br + 32 + hsel * 16, wl + hsel * 8);
            asm volatile("cp.async.commit_group;");
        }

        for (int s = 0; s < nsteps; ++s) {
            if (s + 1 < nsteps) {
                const int k0 = (s + 1) * 16;
                const uint32_t buf = (s + 1) & 1;
                cp16(aS + buf * BUFA + lrow * (PITCH_A * 2) + hsel * 16,
                     Xh + (size_t)lrow * DD + k0 + hsel * 8);
                const uint32_t br = bS + buf * BUFB + lrow * (PITCH_B * 2);
                const __half* wh = Wh + (size_t)(n0 + lrow) * DD + k0;
                const __half* wl = Wl + (size_t)(n0 + lrow) * DD + k0;
                cp16(br + hsel * 16, wh + hsel * 8);
                cp16(br + 32 + hsel * 16, wl + hsel * 8);
                asm volatile("cp.async.commit_group;");
                asm volatile("cp.async.wait_group 1;");
            } else {
                asm volatile("cp.async.wait_group 0;");
            }
            __syncthreads();

            if (s < sbound) {
                const uint32_t cur = s & 1;
                uint32_t ah[4][4];
                #pragma unroll
                for (int mt = 0; mt < 4; ++mt) {
                    const uint32_t ad = aS + cur * BUFA
                        + (uint32_t)((wm * 64 + mt * 16 + (lane & 15)) * (PITCH_A * 2))
                        + (uint32_t)((lane >> 4) * 16);
                    ldmx4(ah[mt], ad);
                }
                #pragma unroll
                for (int nb = 0; nb < 2; ++nb) {
                    uint32_t bh[4], bl[4];
                    const uint32_t bd = bS + cur * BUFB
                        + (uint32_t)((wn * 32 + nb * 16 + brow) * (PITCH_B * 2))
                        + (uint32_t)(bcol * 2);
                    ldmx4(bh, bd);
                    ldmx4(bl, bd + 32);
                    #pragma unroll
                    for (int mt = 0; mt < 4; ++mt) {
                        #pragma unroll
                        for (int h = 0; h < 2; ++h) {
                            float* d = acc[mt][nb * 2 + h];
                            mma16816h(d, ah[mt], &bh[h * 2]);
                            mma16816h(d, ah[mt], &bl[h * 2]);
                        }
                    }
                }
            }
            __syncthreads();
        }

        #pragma unroll
        for (int mt = 0; mt < 4; ++mt)
            #pragma unroll
            for (int jc = 0; jc < 4; ++jc) {
                const int coln = n0 + wn * 32 + (jc >> 1) * 16 + (jc & 1) * 8 + (lane & 3) * 2;
                const float u0 = sU[coln], u1 = sU[coln + 1];
                float z0 = acc[mt][jc][0] - u0, z1 = acc[mt][jc][1] - u1;
                float z2 = acc[mt][jc][2] - u0, z3 = acc[mt][jc][3] - u1;
                distacc[mt * 2 + 0] += z0 * z0 + z1 * z1;
                distacc[mt * 2 + 1] += z2 * z2 + z3 * z3;
            }
    }

    #pragma unroll
    for (int i = 0; i < 8; ++i) {
        distacc[i] += __shfl_xor_sync(0xffffffff, distacc[i], 1);
        distacc[i] += __shfl_xor_sync(0xffffffff, distacc[i], 2);
    }
    if ((lane & 3) == 0) {
        const int r = lane >> 2;
        #pragma unroll
        for (int mt = 0; mt < 4; ++mt) {
            red[wm * 64 + mt * 16 + r][wn]     = distacc[mt * 2 + 0];
            red[wm * 64 + mt * 16 + r + 8][wn] = distacc[mt * 2 + 1];
        }
    }
    __syncthreads();
    if (tid < 128)
        g_dist[(size_t)(b0 + tid) * GG + g] =
            red[tid][0] + red[tid][1] + red[tid][2] + red[tid][3];
}

// ---------------------------------------------------------------------------
// Kernel 5: out = -mean_b( min_g relu(dist[b,g]) ) / 10000
// ---------------------------------------------------------------------------
__global__ __launch_bounds__(256, 1)
void reduce_kernel(float* __restrict__ out)
{
    __shared__ float sh[256];
    float s = 0.f;
    for (int b = threadIdx.x; b < BSZ; b += 256) {
        const float* row = g_dist + (size_t)b * GG;
        float m = fmaxf(row[0], 0.f);
        #pragma unroll 8
        for (int gi = 1; gi < GG; ++gi)
            m = fminf(m, fmaxf(row[gi], 0.f));
        s += m;
    }
    sh[threadIdx.x] = s;
    __syncthreads();
    for (int off = 128; off > 0; off >>= 1) {
        if (threadIdx.x < off) sh[threadIdx.x] += sh[threadIdx.x + off];
        __syncthreads();
    }
    if (threadIdx.x == 0)
        out[0] = -sh[0] / ((float)BSZ * 10000.0f);
}

// ---------------------------------------------------------------------------
extern "C" void kernel_launch(void* const* d_in, const int* in_sizes, int n_in,
                              void* d_out, int out_size)
{
    const float* X    = nullptr;
    const float* mus  = nullptr;
    const float* covs = nullptr;
    for (int i = 0; i < n_in; ++i) {
        if      (in_sizes[i] == BSZ * DD)      X    = (const float*)d_in[i];
        else if (in_sizes[i] == GG * DD)       mus  = (const float*)d_in[i];
        else if (in_sizes[i] == GG * DD * DD)  covs = (const float*)d_in[i];
    }

    static bool attr_done = false;
    if (!attr_done) {
        cudaFuncSetAttribute(trinv_col_kernel,
                             cudaFuncAttributeMaxDynamicSharedMemorySize, T2_SMEM);
        cudaFuncSetAttribute(chol_fused,
                             cudaFuncAttributeMaxDynamicSharedMemorySize, CHOL_SMEM);
        attr_done = true;
    }

    chol_fused<<<GG * 2, 512, CHOL_SMEM>>>(covs);
    diaginv_split_kernel<<<dim3(GG, 4), 128>>>(X);
    trinv_col_kernel<<<dim3(GG, 16), 128, T2_SMEM>>>(mus);
    mma_dist_kernel<<<dim3(BSZ / 128, GG), 256>>>();
    reduce_kernel<<<1, 256>>>((float*)d_out);
}

// round 15
// speedup vs baseline: 1.0543x; 1.0543x over previous
#include <cuda_runtime.h>
#include <cuda_fp16.h>
#include <math.h>
#include <stdint.h>

// Problem sizes (fixed by the reference)
#define BSZ 2048
#define GG  64
#define DD  512
#define DD2 (DD * DD)
#define NB  32
#define PNL 64

// ---------------------------------------------------------------------------
// Scratch (device globals)
// ---------------------------------------------------------------------------
__device__ __align__(16) float g_L[GG * DD2];
__device__ __align__(16) float g_Dinv[GG * 16 * NB * NB];
__device__ __align__(16) float g_u[GG * DD];
__device__ __align__(16) float g_dist[BSZ * GG];
__device__ __align__(16) __half g_Xh[BSZ * DD];
__device__ __align__(16) __half g_Wthi[GG * DD2];
__device__ __align__(16) __half g_Wtlo[GG * DD2];

#define CLUSTER_SYNC() do { \
    asm volatile("barrier.cluster.arrive.aligned;" ::: "memory"); \
    asm volatile("barrier.cluster.wait.aligned;"   ::: "memory"); \
} while (0)

// ---------------------------------------------------------------------------
// mma.sync / cp.async helpers (portable sm_80+ path)
// ---------------------------------------------------------------------------
__device__ __forceinline__ void ldmx4(uint32_t* r, uint32_t addr) {
    asm volatile("ldmatrix.sync.aligned.m8n8.x4.shared.b16 {%0,%1,%2,%3}, [%4];"
                 : "=r"(r[0]), "=r"(r[1]), "=r"(r[2]), "=r"(r[3]) : "r"(addr));
}
__device__ __forceinline__ void mma16816h(float* d, const uint32_t* a, const uint32_t* b) {
    asm volatile(
        "mma.sync.aligned.m16n8k16.row.col.f32.f16.f16.f32 "
        "{%0,%1,%2,%3}, {%4,%5,%6,%7}, {%8,%9}, {%0,%1,%2,%3};"
        : "+f"(d[0]), "+f"(d[1]), "+f"(d[2]), "+f"(d[3])
        : "r"(a[0]), "r"(a[1]), "r"(a[2]), "r"(a[3]), "r"(b[0]), "r"(b[1]));
}
__device__ __forceinline__ void cp16(uint32_t s, const void* g) {
    asm volatile("cp.async.ca.shared.global [%0], [%1], 16;" :: "r"(s), "l"(g));
}

// ---------------------------------------------------------------------------
// Warp-level 32x32 Cholesky in REGISTERS (lane = row, shfl column broadcast).
// ---------------------------------------------------------------------------
__device__ __forceinline__ void warp_chol32(float (*s)[PNL + 1], int roff, int coff,
                                            float* rdiag)
{
    const int lane = threadIdx.x;
    float x[32];
    #pragma unroll
    for (int j = 0; j < 32; ++j) x[j] = s[roff + lane][coff + j];

    float myrs = 0.f;
    #pragma unroll
    for (int k = 0; k < 32; ++k) {
        float dval = __shfl_sync(0xffffffffu, x[k], k);
        float rs = rsqrtf(dval);
        if (lane == k) { x[k] = dval * rs; myrs = rs; }
        float lik = (lane > k) ? x[k] * rs : 0.f;
        if (lane > k) x[k] = lik;
        #pragma unroll
        for (int j = k + 1; j < 32; ++j) {
            float ljk = __shfl_sync(0xffffffffu, lik, j);
            x[j] -= lik * ljk;
        }
    }
    #pragma unroll
    for (int j = 0; j < 32; ++j) s[roff + lane][coff + j] = x[j];
    rdiag[roff + lane] = myrs;
}

// ---------------------------------------------------------------------------
// Kernel 1: fused blocked Cholesky (R13 WIN state, unchanged).
// ---------------------------------------------------------------------------
#define CHOL_SMEM ((64*65 + 64 + 3*64*68) * 4)

__global__ __launch_bounds__(512) __cluster_dims__(2, 1, 1)
void chol_fused(const float* __restrict__ covs)
{
    extern __shared__ float smc[];
    float (*s11)[PNL + 1] = (float(*)[PNL + 1])smc;
    float* rdiag          = smc + 64 * 65;
    float (*Pi)[68]       = (float(*)[68])(smc + 64 * 65 + 64);
    float (*Pj0)[68]      = (float(*)[68])(smc + 64 * 65 + 64 + 64 * 68);
    float (*Pj1)[68]      = (float(*)[68])(smc + 64 * 65 + 64 + 2 * 64 * 68);

    const int g = blockIdx.x >> 1;
    unsigned crank;
    asm("mov.u32 %0, %%cluster_ctarank;" : "=r"(crank));
    float* a = g_L + (size_t)g * DD2;
    const float* cv = covs + (size_t)g * DD2;
    const int tid = threadIdx.x;

    const uint32_t sPi  = (uint32_t)__cvta_generic_to_shared(&Pi[0][0]);
    const uint32_t sPj0 = (uint32_t)__cvta_generic_to_shared(&Pj0[0][0]);
    const uint32_t sPj1 = (uint32_t)__cvta_generic_to_shared(&Pj1[0][0]);

    for (int p = 0; p < DD / PNL; ++p) {
        const int base = p * PNL;
        const int r = DD - base - PNL;
        const float* src = (p == 0) ? cv : a;

        for (int q = tid; q < PNL * PNL; q += 512) {
            int i = q & 63, j = q >> 6;
            s11[i][j] = src[(size_t)(base + j) * DD + (base + i)];
        }
        __syncthreads();

        if (tid < 32) warp_chol32(s11, 0, 0, rdiag);
        __syncthreads();

        if (tid < 32) {
            const int row = 32 + tid;
            float x[32];
            #pragma unroll
            for (int j = 0; j < 32; ++j) x[j] = s11[row][j];
            #pragma unroll
            for (int j = 0; j < 32; ++j) {
                float s = x[j];
                #pragma unroll
                for (int k = 0; k < j; ++k)
                    s -= x[k] * s11[j][k];
                x[j] = s * rdiag[j];
            }
            #pragma unroll
            for (int j = 0; j < 32; ++j) s11[row][j] = x[j];
        }
        __syncthreads();

        #pragma unroll
        for (int e = 0; e < 2; ++e) {
            const int idx = tid + e * 512;
            const int i2 = 32 + (idx >> 5);
            const int j2 = 32 + (idx & 31);
            float s = 0.f;
            #pragma unroll
            for (int k = 0; k < 32; ++k)
                s += s11[i2][k] * s11[j2][k];
            s11[i2][j2] -= s;
        }
        __syncthreads();

        if (tid < 32) warp_chol32(s11, 32, 32, rdiag);
        __syncthreads();

        if (crank == 0) {
            for (int q = tid; q < PNL * PNL; q += 512) {
                int i = q & 63, j = q >> 6;
                if (i >= j) a[(size_t)(base + j) * DD + (base + i)] = s11[i][j];
            }
        }

        if (r > 0) {
            const int chunk = r >> 1;
            const int row = (int)crank * chunk + tid;
            if (row < r && tid < chunk) {
                const int gr = base + PNL + row;
                float x[PNL];
                #pragma unroll
                for (int j = 0; j < PNL; ++j)
                    x[j] = src[(size_t)(base + j) * DD + gr];
                #pragma unroll
                for (int j = 0; j < PNL; ++j) {
                    float s = x[j];
                    #pragma unroll
                    for (int k = 0; k < j; ++k)
                        s -= x[k] * s11[j][k];
                    x[j] = s * rdiag[j];
                }
                #pragma unroll
                for (int j = 0; j < PNL; ++j)
                    a[(size_t)(base + j) * DD + gr] = x[j];
            }
        }
        CLUSTER_SYNC();

        if (r > 0) {
            const int m = r >> 6;
            for (int ti = (int)crank; ti < m; ti += 2) {
                const int gi = ti * 64;

                #pragma unroll
                for (int e = 0; e < 2; ++e) {
                    const int f = tid * 2 + e;
                    const int col = f >> 4, r4 = f & 15;
                    cp16(sPi + (uint32_t)((col * 68 + r4 * 4) * 4),
                         a + (size_t)(base + col) * DD + base + PNL + gi + r4 * 4);
                }
                if (ti > 0) {
                    #pragma unroll
                    for (int e = 0; e < 2; ++e) {
                        const int f = tid * 2 + e;
                        const int col = f >> 4, r4 = f & 15;
                        cp16(sPj0 + (uint32_t)((col * 68 + r4 * 4) * 4),
                             a + (size_t)(base + col) * DD + base + PNL + r4 * 4);
                    }
                }
                asm volatile("cp.async.commit_group;");
                asm volatile("cp.async.wait_group 0;");
                __syncthreads();

                for (int tj = 0; tj <= ti; ++tj) {
                    if (tj + 1 < ti) {
                        const int gjn = (tj + 1) * 64;
                        const uint32_t dstb = ((tj + 1) & 1) ? sPj1 : sPj0;
                        #pragma unroll
                        for (int e = 0; e < 2; ++e) {
                            const int f = tid * 2 + e;
                            const int col = f >> 4, r4 = f & 15;
                            cp16(dstb + (uint32_t)((col * 68 + r4 * 4) * 4),
                                 a + (size_t)(base + col) * DD + base + PNL + gjn + r4 * 4);
                        }
                        asm volatile("cp.async.commit_group;");
                    }

                    const int gj = tj * 64;
                    const float (*PJ)[68] = (tj == ti) ? Pi
                                           : ((tj & 1) ? Pj1 : Pj0);
                    const int tx = tid & 15;
                    const int ty = tid >> 4;
                    float acc[4][2];
                    #pragma unroll
                    for (int ii = 0; ii < 4; ++ii) { acc[ii][0] = 0.f; acc[ii][1] = 0.f; }

                    #pragma unroll
                    for (int k = 0; k < PNL; ++k) {
                        float4 pi = *(const float4*)&Pi[k][tx * 4];
                        float2 pj = *(const float2*)&PJ[k][ty * 2];
                        float pr[4] = {pi.x, pi.y, pi.z, pi.w};
                        #pragma unroll
                        for (int ii = 0; ii < 4; ++ii) {
                            acc[ii][0] += pr[ii] * pj.x;
                            acc[ii][1] += pr[ii] * pj.y;
                        }
                    }

                    const int rowb = gi + tx * 4;
                    #pragma unroll
                    for (int jj = 0; jj < 2; ++jj) {
                        const int colg = gj + ty * 2 + jj;
                        const size_t off = (size_t)(base + PNL + colg) * DD + base + PNL + rowb;
                        float4 cvv = *(const float4*)(src + off);
                        cvv.x -= acc[0][jj]; cvv.y -= acc[1][jj];
                        cvv.z -= acc[2][jj]; cvv.w -= acc[3][jj];
                        *(float4*)(a + off) = cvv;
                    }

                    if (tj + 1 < ti) {
                        asm volatile("cp.async.wait_group 0;");
                        __syncthreads();
                    }
                }
            }
        }
        CLUSTER_SYNC();
    }
}

// ---------------------------------------------------------------------------
// Kernel 2a: diag-block inverse + fused X->fp16 conversion (R14 state).
// ---------------------------------------------------------------------------
__global__ __launch_bounds__(128, 8)
void diaginv_split_kernel(const float* __restrict__ X)
{
    __shared__ float su[4][NB][NB + 1];
    __shared__ float sx[4][NB][NB + 1];

    const int g = blockIdx.x;
    const int w = threadIdx.x >> 5;
    const int d = blockIdx.y * 4 + w;
    const int cc = threadIdx.x & 31;
    const float* U = g_L + (size_t)g * DD2;
    const int b0 = d * NB;

    {
        const int blk = blockIdx.y * GG + blockIdx.x;
        const int base = blk * 1024 + threadIdx.x;
        #pragma unroll
        for (int e = 0; e < 8; ++e) {
            const int i = base + e * 128;
            float4 v = ((const float4*)X)[i];
            __half h[4] = {__float2half(v.x), __float2half(v.y),
                           __float2half(v.z), __float2half(v.w)};
            ((uint2*)g_Xh)[i] = *(uint2*)h;
        }
    }

    for (int rr = 0; rr < NB; ++rr)
        su[w][rr][cc] = U[(size_t)(b0 + rr) * DD + (b0 + cc)];
    __syncwarp();

    for (int t = cc; t >= 0; --t) {
        float s = (t == cc) ? 1.f : 0.f;
        for (int ss = t + 1; ss <= cc; ++ss)
            s -= su[w][t][ss] * sx[w][ss][cc];
        sx[w][t][cc] = s / su[w][t][t];
    }
    __syncwarp();

    float* dst = g_Dinv + ((size_t)g * 16 + d) * NB * NB;
    for (int t = 0; t < NB; ++t)
        dst[t * NB + cc] = (t <= cc) ? sx[w][t][cc] : 0.f;
}

// ---------------------------------------------------------------------------
// Kernel 2b: blocked triangular inverse (R13 256-thread version, measured 203us).
// ---------------------------------------------------------------------------
#define T2_SMEM ((512*36 + 4*32*36 + 32*33) * 4)

__global__ __launch_bounds__(256)
void trinv_col_kernel(const float* __restrict__ mus)
{
    extern __shared__ float sm2[];
    float (*Vs)[36] = (float(*)[36])sm2;
    float (*Us)[32][36] = (float(*)[32][36])(sm2 + 512 * 36);
    float (*Ts)[33] = (float(*)[33])(sm2 + 512 * 36 + 4 * 32 * 36);

    const int g = blockIdx.x;
    const int j = 15 - blockIdx.y;
    const float* U = g_L + (size_t)g * DD2;
    const int tid = threadIdx.x;
    const int cc  = tid & 31;
    const int q   = tid >> 5;

    {
        const float* din = g_Dinv + ((size_t)g * 16 + j) * NB * NB;
        #pragma unroll
        for (int t4 = 0; t4 < 4; ++t4) {
            int t = q * 4 + t4;
            Vs[j * NB + t][cc] = din[t * NB + cc];
        }
    }
    __syncthreads();

    for (int i = j - 1; i >= 0; --i) {
        float acc[4];
        #pragma unroll
        for (int r4 = 0; r4 < 4; ++r4) acc[r4] = 0.f;

        for (int kc = i + 1; kc <= j; kc += 4) {
            const int nk = (j - kc + 1 < 4) ? (j - kc + 1) : 4;
            for (int b = 0; b < nk; ++b) {
                const float* ub = U + (size_t)(i * NB) * DD + (kc + b) * NB;
                const int rr = tid >> 3, t4 = tid & 7;
                *(float4*)&Us[b][rr][t4 * 4] = *(const float4*)&ub[(size_t)rr * DD + t4 * 4];
            }
            __syncthreads();
            for (int b = 0; b < nk; ++b) {
                const int k = kc + b;
                #pragma unroll
                for (int t4 = 0; t4 < 8; ++t4) {
                    float v0 = Vs[k * NB + t4 * 4 + 0][cc];
                    float v1 = Vs[k * NB + t4 * 4 + 1][cc];
                    float v2 = Vs[k * NB + t4 * 4 + 2][cc];
                    float v3 = Vs[k * NB + t4 * 4 + 3][cc];
                    #pragma unroll
                    for (int r4 = 0; r4 < 4; ++r4) {
                        float4 u4 = *(const float4*)&Us[b][q * 4 + r4][t4 * 4];
                        acc[r4] += u4.x * v0 + u4.y * v1 + u4.z * v2 + u4.w * v3;
                    }
                }
            }
            __syncthreads();
        }

        #pragma unroll
        for (int r4 = 0; r4 < 4; ++r4) Ts[q * 4 + r4][cc] = acc[r4];
        {
            const float* din = g_Dinv + ((size_t)g * 16 + i) * NB * NB;
            const int rr = tid >> 3, t4 = tid & 7;
            *(float4*)&Us[0][rr][t4 * 4] = *(const float4*)&din[rr * NB + t4 * 4];
        }
        __syncthreads();

        float acc2[4];
        #pragma unroll
        for (int r4 = 0; r4 < 4; ++r4) acc2[r4] = 0.f;
        #pragma unroll
        for (int t4 = 0; t4 < 8; ++t4) {
            float v0 = Ts[t4 * 4 + 0][cc];
            float v1 = Ts[t4 * 4 + 1][cc];
            float v2 = Ts[t4 * 4 + 2][cc];
            float v3 = Ts[t4 * 4 + 3][cc];
            #pragma unroll
            for (int r4 = 0; r4 < 4; ++r4) {
                float4 u4 = *(const float4*)&Us[0][q * 4 + r4][t4 * 4];
                acc2[r4] += u4.x * v0 + u4.y * v1 + u4.z * v2 + u4.w * v3;
            }
        }
        #pragma unroll
        for (int r4 = 0; r4 < 4; ++r4) Vs[i * NB + q * 4 + r4][cc] = -acc2[r4];
        __syncthreads();
    }

    {
        __half* Whi = g_Wthi + (size_t)g * DD2;
        __half* Wlo = g_Wtlo + (size_t)g * DD2;
        const int kmax  = (j + 1) * NB;
        const int kfill = 128 * ((j >> 2) + 1);
        for (int nl = q; nl < NB; nl += 8) {
            const size_t nbase = (size_t)(j * NB + nl) * DD;
            for (int k = cc; k < kmax; k += 32) {
                float f = Vs[k][nl];
                __half h = __float2half(f);
                __half l = __float2half(f - __half2float(h));
                Whi[nbase + k] = h;
                Wlo[nbase + k] = l;
            }
            for (int k = kmax + cc; k < kfill; k += 32) {
                Whi[nbase + k] = __float2half(0.f);
                Wlo[nbase + k] = __float2half(0.f);
            }
        }
    }

    {
        const float* mu = mus + (size_t)g * DD;
        float s = 0.f;
        for (int row = q; row < (j + 1) * NB; row += 8)
            s += mu[row] * Vs[row][cc];
        __syncthreads();
        Ts[q][cc] = s;
        __syncthreads();
        if (q == 0) {
            float tot = 0.f;
            #pragma unroll
            for (int w8 = 0; w8 < 8; ++w8) tot += Ts[w8][cc];
            g_u[(size_t)g * DD + j * NB + cc] = tot;
        }
    }
}

// ---------------------------------------------------------------------------
// Kernel 4: fp16 2-product GEMM via mma.sync + fused dist epilogue.
// v3: 3-stage cp.async ring, ONE __syncthreads per k-stage (the 3rd buffer
// makes the post-compute barrier provably unnecessary). Dynamic smem.
// ---------------------------------------------------------------------------
#define PITCH_A 24
#define PITCH_B 40
#define A_STAGE (128 * PITCH_A)              // halfs
#define B_STAGE (128 * PITCH_B)
#define MMA_SMEM ((3 * (A_STAGE + B_STAGE)) * 2 + 512 * 4 + 128 * 4 * 4)

__global__ __launch_bounds__(256, 2)
void mma_dist_kernel()
{
    extern __shared__ char smraw[];
    __half* As = (__half*)smraw;                               // [3][128][PITCH_A]
    __half* Bs = (__half*)(smraw + 3 * A_STAGE * 2);           // [3][128][PITCH_B]
    float* sU  = (float*)(smraw + 3 * (A_STAGE + B_STAGE) * 2);
    float (*red)[4] = (float(*)[4])(smraw + 3 * (A_STAGE + B_STAGE) * 2 + 512 * 4);

    const int tid  = threadIdx.x;
    const int lane = tid & 31;
    const int wid  = tid >> 5;
    const int wm   = wid & 1;
    const int wn   = wid >> 1;
    const int g    = blockIdx.y;
    const int b0   = blockIdx.x * 128;

    for (int c = tid; c < 512; c += 256) sU[c] = g_u[(size_t)g * DD + c];

    const __half* Xh = g_Xh + (size_t)b0 * DD;
    const __half* Wh = g_Wthi + (size_t)g * DD2;
    const __half* Wl = g_Wtlo + (size_t)g * DD2;

    const uint32_t aS = (uint32_t)__cvta_generic_to_shared(As);
    const uint32_t bS = (uint32_t)__cvta_generic_to_shared(Bs);
    const uint32_t BUFA = A_STAGE * 2;       // bytes per stage
    const uint32_t BUFB = B_STAGE * 2;

    const int lrow = tid >> 1;
    const int hsel = tid & 1;
    const int brow = ((lane >> 4) << 3) + (lane & 7);
    const int bcol = ((lane >> 3) & 1) * 8;

    float distacc[8];
    #pragma unroll
    for (int i = 0; i < 8; ++i) distacc[i] = 0.f;

    __syncthreads();   // sU visible

    for (int nt = 0; nt < 4; ++nt) {
        const int n0 = nt * 128;
        const int nsteps = (nt + 1) * 8;
        const int sbound = nt * 8 + 2 * wn + 2;

        float acc[4][4][4];
        #pragma unroll
        for (int mt = 0; mt < 4; ++mt)
            #pragma unroll
            for (int jc = 0; jc < 4; ++jc)
                #pragma unroll
                for (int e = 0; e < 4; ++e) acc[mt][jc][e] = 0.f;

        // prologue: issue stages 0 and 1
        #pragma unroll
        for (int ps = 0; ps < 2; ++ps) {
            if (ps < nsteps) {
                const int k0 = ps * 16;
                cp16(aS + ps * BUFA + lrow * (PITCH_A * 2) + hsel * 16,
                     Xh + (size_t)lrow * DD + k0 + hsel * 8);
                const uint32_t br = bS + ps * BUFB + lrow * (PITCH_B * 2);
                const __half* wh = Wh + (size_t)(n0 + lrow) * DD + k0;
                const __half* wl = Wl + (size_t)(n0 + lrow) * DD + k0;
                cp16(br + hsel * 16, wh + hsel * 8);
                cp16(br + 32 + hsel * 16, wl + hsel * 8);
                asm volatile("cp.async.commit_group;");
            }
        }

        for (int s = 0; s < nsteps; ++s) {
            if (s + 1 < nsteps)
                asm volatile("cp.async.wait_group 1;");
            else
                asm volatile("cp.async.wait_group 0;");
            __syncthreads();

            if (s < sbound) {
                const uint32_t cur = (uint32_t)(s % 3);
                uint32_t ah[4][4];
                #pragma unroll
                for (int mt = 0; mt < 4; ++mt) {
                    const uint32_t ad = aS + cur * BUFA
                        + (uint32_t)((wm * 64 + mt * 16 + (lane & 15)) * (PITCH_A * 2))
                        + (uint32_t)((lane >> 4) * 16);
                    ldmx4(ah[mt], ad);
                }
                #pragma unroll
                for (int nb = 0; nb < 2; ++nb) {
                    uint32_t bh[4], bl[4];
                    const uint32_t bd = bS + cur * BUFB
                        + (uint32_t)((wn * 32 + nb * 16 + brow) * (PITCH_B * 2))
                        + (uint32_t)(bcol * 2);
                    ldmx4(bh, bd);
                    ldmx4(bl, bd + 32);
                    #pragma unroll
                    for (int mt = 0; mt < 4; ++mt) {
                        #pragma unroll
                        for (int h = 0; h < 2; ++h) {
                            float* d = acc[mt][nb * 2 + h];
                            mma16816h(d, ah[mt], &bh[h * 2]);
                            mma16816h(d, ah[mt], &bl[h * 2]);
                        }
                    }
                }
            }

            // issue stage s+2 into buffer (s+2)%3 — its previous occupant
            // (stage s-1) was fully consumed before this iteration's barrier.
            if (s + 2 < nsteps) {
                const int k0 = (s + 2) * 16;
                const uint32_t nb3 = (uint32_t)((s + 2) % 3);
                cp16(aS + nb3 * BUFA + lrow * (PITCH_A * 2) + hsel * 16,
                     Xh + (size_t)lrow * DD + k0 + hsel * 8);
                const uint32_t br = bS + nb3 * BUFB + lrow * (PITCH_B * 2);
                const __half* wh = Wh + (size_t)(n0 + lrow) * DD + k0;
                const __half* wl = Wl + (size_t)(n0 + lrow) * DD + k0;
                cp16(br + hsel * 16, wh + hsel * 8);
                cp16(br + 32 + hsel * 16, wl + hsel * 8);
                asm volatile("cp.async.commit_group;");
            }
        }

        // fold (z-u)^2
        #pragma unroll
        for (int mt = 0; mt < 4; ++mt)
            #pragma unroll
            for (int jc = 0; jc < 4; ++jc) {
                const int coln = n0 + wn * 32 + (jc >> 1) * 16 + (jc & 1) * 8 + (lane & 3) * 2;
                const float u0 = sU[coln], u1 = sU[coln + 1];
                float z0 = acc[mt][jc][0] - u0, z1 = acc[mt][jc][1] - u1;
                float z2 = acc[mt][jc][2] - u0, z3 = acc[mt][jc][3] - u1;
                distacc[mt * 2 + 0] += z0 * z0 + z1 * z1;
                distacc[mt * 2 + 1] += z2 * z2 + z3 * z3;
            }
        __syncthreads();   // buffer recycle across nt boundary
    }

    #pragma unroll
    for (int i = 0; i < 8; ++i) {
        distacc[i] += __shfl_xor_sync(0xffffffff, distacc[i], 1);
        distacc[i] += __shfl_xor_sync(0xffffffff, distacc[i], 2);
    }
    if ((lane & 3) == 0) {
        const int r = lane >> 2;
        #pragma unroll
        for (int mt = 0; mt < 4; ++mt) {
            red[wm * 64 + mt * 16 + r][wn]     = distacc[mt * 2 + 0];
            red[wm * 64 + mt * 16 + r + 8][wn] = distacc[mt * 2 + 1];
        }
    }
    __syncthreads();
    if (tid < 128)
        g_dist[(size_t)(b0 + tid) * GG + g] =
            red[tid][0] + red[tid][1] + red[tid][2] + red[tid][3];
}

// ---------------------------------------------------------------------------
// Kernel 5: out = -mean_b( min_g relu(dist[b,g]) ) / 10000
// ---------------------------------------------------------------------------
__global__ __launch_bounds__(256, 1)
void reduce_kernel(float* __restrict__ out)
{
    __shared__ float sh[256];
    float s = 0.f;
    for (int b = threadIdx.x; b < BSZ; b += 256) {
        const float* row = g_dist + (size_t)b * GG;
        float m = fmaxf(row[0], 0.f);
        #pragma unroll 8
        for (int gi = 1; gi < GG; ++gi)
            m = fminf(m, fmaxf(row[gi], 0.f));
        s += m;
    }
    sh[threadIdx.x] = s;
    __syncthreads();
    for (int off = 128; off > 0; off >>= 1) {
        if (threadIdx.x < off) sh[threadIdx.x] += sh[threadIdx.x + off];
        __syncthreads();
    }
    if (threadIdx.x == 0)
        out[0] = -sh[0] / ((float)BSZ * 10000.0f);
}

// ---------------------------------------------------------------------------
extern "C" void kernel_launch(void* const* d_in, const int* in_sizes, int n_in,
                              void* d_out, int out_size)
{
    const float* X    = nullptr;
    const float* mus  = nullptr;
    const float* covs = nullptr;
    for (int i = 0; i < n_in; ++i) {
        if      (in_sizes[i] == BSZ * DD)      X    = (const float*)d_in[i];
        else if (in_sizes[i] == GG * DD)       mus  = (const float*)d_in[i];
        else if (in_sizes[i] == GG * DD * DD)  covs = (const float*)d_in[i];
    }

    static bool attr_done = false;
    if (!attr_done) {
        cudaFuncSetAttribute(trinv_col_kernel,
                             cudaFuncAttributeMaxDynamicSharedMemorySize, T2_SMEM);
        cudaFuncSetAttribute(chol_fused,
                             cudaFuncAttributeMaxDynamicSharedMemorySize, CHOL_SMEM);
        cudaFuncSetAttribute(mma_dist_kernel,
                             cudaFuncAttributeMaxDynamicSharedMemorySize, MMA_SMEM);
        attr_done = true;
    }

    chol_fused<<<GG * 2, 512, CHOL_SMEM>>>(covs);
    diaginv_split_kernel<<<dim3(GG, 4), 128>>>(X);
    trinv_col_kernel<<<dim3(GG, 16), 256, T2_SMEM>>>(mus);
    mma_dist_kernel<<<dim3(BSZ / 128, GG), 256, MMA_SMEM>>>();
    reduce_kernel<<<1, 256>>>((float*)d_out);
}

// round 16
// speedup vs baseline: 1.0607x; 1.0061x over previous
#include <cuda_runtime.h>
#include <cuda_fp16.h>
#include <math.h>
#include <stdint.h>

// Problem sizes (fixed by the reference)
#define BSZ 2048
#define GG  64
#define DD  512
#define DD2 (DD * DD)
#define NB  32
#define PNL 64

// ---------------------------------------------------------------------------
// Scratch (device globals)
// ---------------------------------------------------------------------------
__device__ __align__(16) float g_L[GG * DD2];
__device__ __align__(16) float g_Dinv[GG * 16 * NB * NB];
__device__ __align__(16) float g_u[GG * DD];
__device__ __align__(16) float g_dist[BSZ * GG];
__device__ __align__(16) __half g_Xh[BSZ * DD];
__device__ __align__(16) __half g_Wthi[GG * DD2];
__device__ __align__(16) __half g_Wtlo[GG * DD2];

#define CLUSTER_SYNC() do { \
    asm volatile("barrier.cluster.arrive.aligned;" ::: "memory"); \
    asm volatile("barrier.cluster.wait.aligned;"   ::: "memory"); \
} while (0)

// ---------------------------------------------------------------------------
// mma.sync / cp.async helpers
// ---------------------------------------------------------------------------
__device__ __forceinline__ void ldmx4(uint32_t* r, uint32_t addr) {
    asm volatile("ldmatrix.sync.aligned.m8n8.x4.shared.b16 {%0,%1,%2,%3}, [%4];"
                 : "=r"(r[0]), "=r"(r[1]), "=r"(r[2]), "=r"(r[3]) : "r"(addr));
}
__device__ __forceinline__ void mma16816h(float* d, const uint32_t* a, const uint32_t* b) {
    asm volatile(
        "mma.sync.aligned.m16n8k16.row.col.f32.f16.f16.f32 "
        "{%0,%1,%2,%3}, {%4,%5,%6,%7}, {%8,%9}, {%0,%1,%2,%3};"
        : "+f"(d[0]), "+f"(d[1]), "+f"(d[2]), "+f"(d[3])
        : "r"(a[0]), "r"(a[1]), "r"(a[2]), "r"(a[3]), "r"(b[0]), "r"(b[1]));
}
__device__ __forceinline__ void cp16(uint32_t s, const void* g) {
    asm volatile("cp.async.ca.shared.global [%0], [%1], 16;" :: "r"(s), "l"(g));
}

// ---------------------------------------------------------------------------
// Warp-level 32x32 Cholesky in REGISTERS (lane = row, shfl column broadcast).
// ---------------------------------------------------------------------------
__device__ __forceinline__ void warp_chol32(float (*s)[PNL + 1], int roff, int coff,
                                            float* rdiag)
{
    const int lane = threadIdx.x;
    float x[32];
    #pragma unroll
    for (int j = 0; j < 32; ++j) x[j] = s[roff + lane][coff + j];

    float myrs = 0.f;
    #pragma unroll
    for (int k = 0; k < 32; ++k) {
        float dval = __shfl_sync(0xffffffffu, x[k], k);
        float rs = rsqrtf(dval);
        if (lane == k) { x[k] = dval * rs; myrs = rs; }
        float lik = (lane > k) ? x[k] * rs : 0.f;
        if (lane > k) x[k] = lik;
        #pragma unroll
        for (int j = k + 1; j < 32; ++j) {
            float ljk = __shfl_sync(0xffffffffu, lik, j);
            x[j] -= lik * ljk;
        }
    }
    #pragma unroll
    for (int j = 0; j < 32; ++j) s[roff + lane][coff + j] = x[j];
    rdiag[roff + lane] = myrs;
}

// ---------------------------------------------------------------------------
// Kernel 1: fused blocked Cholesky (R13 WIN state, unchanged).
// ---------------------------------------------------------------------------
#define CHOL_SMEM ((64*65 + 64 + 3*64*68) * 4)

__global__ __launch_bounds__(512) __cluster_dims__(2, 1, 1)
void chol_fused(const float* __restrict__ covs)
{
    extern __shared__ float smc[];
    float (*s11)[PNL + 1] = (float(*)[PNL + 1])smc;
    float* rdiag          = smc + 64 * 65;
    float (*Pi)[68]       = (float(*)[68])(smc + 64 * 65 + 64);
    float (*Pj0)[68]      = (float(*)[68])(smc + 64 * 65 + 64 + 64 * 68);
    float (*Pj1)[68]      = (float(*)[68])(smc + 64 * 65 + 64 + 2 * 64 * 68);

    const int g = blockIdx.x >> 1;
    unsigned crank;
    asm("mov.u32 %0, %%cluster_ctarank;" : "=r"(crank));
    float* a = g_L + (size_t)g * DD2;
    const float* cv = covs + (size_t)g * DD2;
    const int tid = threadIdx.x;

    const uint32_t sPi  = (uint32_t)__cvta_generic_to_shared(&Pi[0][0]);
    const uint32_t sPj0 = (uint32_t)__cvta_generic_to_shared(&Pj0[0][0]);
    const uint32_t sPj1 = (uint32_t)__cvta_generic_to_shared(&Pj1[0][0]);

    for (int p = 0; p < DD / PNL; ++p) {
        const int base = p * PNL;
        const int r = DD - base - PNL;
        const float* src = (p == 0) ? cv : a;

        for (int q = tid; q < PNL * PNL; q += 512) {
            int i = q & 63, j = q >> 6;
            s11[i][j] = src[(size_t)(base + j) * DD + (base + i)];
        }
        __syncthreads();

        if (tid < 32) warp_chol32(s11, 0, 0, rdiag);
        __syncthreads();

        if (tid < 32) {
            const int row = 32 + tid;
            float x[32];
            #pragma unroll
            for (int j = 0; j < 32; ++j) x[j] = s11[row][j];
            #pragma unroll
            for (int j = 0; j < 32; ++j) {
                float s = x[j];
                #pragma unroll
                for (int k = 0; k < j; ++k)
                    s -= x[k] * s11[j][k];
                x[j] = s * rdiag[j];
            }
            #pragma unroll
            for (int j = 0; j < 32; ++j) s11[row][j] = x[j];
        }
        __syncthreads();

        #pragma unroll
        for (int e = 0; e < 2; ++e) {
            const int idx = tid + e * 512;
            const int i2 = 32 + (idx >> 5);
            const int j2 = 32 + (idx & 31);
            float s = 0.f;
            #pragma unroll
            for (int k = 0; k < 32; ++k)
                s += s11[i2][k] * s11[j2][k];
            s11[i2][j2] -= s;
        }
        __syncthreads();

        if (tid < 32) warp_chol32(s11, 32, 32, rdiag);
        __syncthreads();

        if (crank == 0) {
            for (int q = tid; q < PNL * PNL; q += 512) {
                int i = q & 63, j = q >> 6;
                if (i >= j) a[(size_t)(base + j) * DD + (base + i)] = s11[i][j];
            }
        }

        if (r > 0) {
            const int chunk = r >> 1;
            const int row = (int)crank * chunk + tid;
            if (row < r && tid < chunk) {
                const int gr = base + PNL + row;
                float x[PNL];
                #pragma unroll
                for (int j = 0; j < PNL; ++j)
                    x[j] = src[(size_t)(base + j) * DD + gr];
                #pragma unroll
                for (int j = 0; j < PNL; ++j) {
                    float s = x[j];
                    #pragma unroll
                    for (int k = 0; k < j; ++k)
                        s -= x[k] * s11[j][k];
                    x[j] = s * rdiag[j];
                }
                #pragma unroll
                for (int j = 0; j < PNL; ++j)
                    a[(size_t)(base + j) * DD + gr] = x[j];
            }
        }
        CLUSTER_SYNC();

        if (r > 0) {
            const int m = r >> 6;
            for (int ti = (int)crank; ti < m; ti += 2) {
                const int gi = ti * 64;

                #pragma unroll
                for (int e = 0; e < 2; ++e) {
                    const int f = tid * 2 + e;
                    const int col = f >> 4, r4 = f & 15;
                    cp16(sPi + (uint32_t)((col * 68 + r4 * 4) * 4),
                         a + (size_t)(base + col) * DD + base + PNL + gi + r4 * 4);
                }
                if (ti > 0) {
                    #pragma unroll
                    for (int e = 0; e < 2; ++e) {
                        const int f = tid * 2 + e;
                        const int col = f >> 4, r4 = f & 15;
                        cp16(sPj0 + (uint32_t)((col * 68 + r4 * 4) * 4),
                             a + (size_t)(base + col) * DD + base + PNL + r4 * 4);
                    }
                }
                asm volatile("cp.async.commit_group;");
                asm volatile("cp.async.wait_group 0;");
                __syncthreads();

                for (int tj = 0; tj <= ti; ++tj) {
                    if (tj + 1 < ti) {
                        const int gjn = (tj + 1) * 64;
                        const uint32_t dstb = ((tj + 1) & 1) ? sPj1 : sPj0;
                        #pragma unroll
                        for (int e = 0; e < 2; ++e) {
                            const int f = tid * 2 + e;
                            const int col = f >> 4, r4 = f & 15;
                            cp16(dstb + (uint32_t)((col * 68 + r4 * 4) * 4),
                                 a + (size_t)(base + col) * DD + base + PNL + gjn + r4 * 4);
                        }
                        asm volatile("cp.async.commit_group;");
                    }

                    const int gj = tj * 64;
                    const float (*PJ)[68] = (tj == ti) ? Pi
                                           : ((tj & 1) ? Pj1 : Pj0);
                    const int tx = tid & 15;
                    const int ty = tid >> 4;
                    float acc[4][2];
                    #pragma unroll
                    for (int ii = 0; ii < 4; ++ii) { acc[ii][0] = 0.f; acc[ii][1] = 0.f; }

                    #pragma unroll
                    for (int k = 0; k < PNL; ++k) {
                        float4 pi = *(const float4*)&Pi[k][tx * 4];
                        float2 pj = *(const float2*)&PJ[k][ty * 2];
                        float pr[4] = {pi.x, pi.y, pi.z, pi.w};
                        #pragma unroll
                        for (int ii = 0; ii < 4; ++ii) {
                            acc[ii][0] += pr[ii] * pj.x;
                            acc[ii][1] += pr[ii] * pj.y;
                        }
                    }

                    const int rowb = gi + tx * 4;
                    #pragma unroll
                    for (int jj = 0; jj < 2; ++jj) {
                        const int colg = gj + ty * 2 + jj;
                        const size_t off = (size_t)(base + PNL + colg) * DD + base + PNL + rowb;
                        float4 cvv = *(const float4*)(src + off);
                        cvv.x -= acc[0][jj]; cvv.y -= acc[1][jj];
                        cvv.z -= acc[2][jj]; cvv.w -= acc[3][jj];
                        *(float4*)(a + off) = cvv;
                    }

                    if (tj + 1 < ti) {
                        asm volatile("cp.async.wait_group 0;");
                        __syncthreads();
                    }
                }
            }
        }
        CLUSTER_SYNC();
    }
}

// ---------------------------------------------------------------------------
// Kernel 2a: diag-block inverse + fused X->fp16 conversion (unchanged).
// ---------------------------------------------------------------------------
__global__ __launch_bounds__(128, 8)
void diaginv_split_kernel(const float* __restrict__ X)
{
    __shared__ float su[4][NB][NB + 1];
    __shared__ float sx[4][NB][NB + 1];

    const int g = blockIdx.x;
    const int w = threadIdx.x >> 5;
    const int d = blockIdx.y * 4 + w;
    const int cc = threadIdx.x & 31;
    const float* U = g_L + (size_t)g * DD2;
    const int b0 = d * NB;

    {
        const int blk = blockIdx.y * GG + blockIdx.x;
        const int base = blk * 1024 + threadIdx.x;
        #pragma unroll
        for (int e = 0; e < 8; ++e) {
            const int i = base + e * 128;
            float4 v = ((const float4*)X)[i];
            __half h[4] = {__float2half(v.x), __float2half(v.y),
                           __float2half(v.z), __float2half(v.w)};
            ((uint2*)g_Xh)[i] = *(uint2*)h;
        }
    }

    for (int rr = 0; rr < NB; ++rr)
        su[w][rr][cc] = U[(size_t)(b0 + rr) * DD + (b0 + cc)];
    __syncwarp();

    for (int t = cc; t >= 0; --t) {
        float s = (t == cc) ? 1.f : 0.f;
        for (int ss = t + 1; ss <= cc; ++ss)
            s -= su[w][t][ss] * sx[w][ss][cc];
        sx[w][t][cc] = s / su[w][t][t];
    }
    __syncwarp();

    float* dst = g_Dinv + ((size_t)g * 16 + d) * NB * NB;
    for (int t = 0; t < NB; ++t)
        dst[t * NB + cc] = (t <= cc) ? sx[w][t][cc] : 0.f;
}

// ---------------------------------------------------------------------------
// Kernel 2b: blocked triangular inverse (R13 measured-best version).
// ---------------------------------------------------------------------------
#define T2_SMEM ((512*36 + 4*32*36 + 32*33) * 4)

__global__ __launch_bounds__(256)
void trinv_col_kernel(const float* __restrict__ mus)
{
    extern __shared__ float sm2[];
    float (*Vs)[36] = (float(*)[36])sm2;
    float (*Us)[32][36] = (float(*)[32][36])(sm2 + 512 * 36);
    float (*Ts)[33] = (float(*)[33])(sm2 + 512 * 36 + 4 * 32 * 36);

    const int g = blockIdx.x;
    const int j = 15 - blockIdx.y;
    const float* U = g_L + (size_t)g * DD2;
    const int tid = threadIdx.x;
    const int cc  = tid & 31;
    const int q   = tid >> 5;

    {
        const float* din = g_Dinv + ((size_t)g * 16 + j) * NB * NB;
        #pragma unroll
        for (int t4 = 0; t4 < 4; ++t4) {
            int t = q * 4 + t4;
            Vs[j * NB + t][cc] = din[t * NB + cc];
        }
    }
    __syncthreads();

    for (int i = j - 1; i >= 0; --i) {
        float acc[4];
        #pragma unroll
        for (int r4 = 0; r4 < 4; ++r4) acc[r4] = 0.f;

        for (int kc = i + 1; kc <= j; kc += 4) {
            const int nk = (j - kc + 1 < 4) ? (j - kc + 1) : 4;
            for (int b = 0; b < nk; ++b) {
                const float* ub = U + (size_t)(i * NB) * DD + (kc + b) * NB;
                const int rr = tid >> 3, t4 = tid & 7;
                *(float4*)&Us[b][rr][t4 * 4] = *(const float4*)&ub[(size_t)rr * DD + t4 * 4];
            }
            __syncthreads();
            for (int b = 0; b < nk; ++b) {
                const int k = kc + b;
                #pragma unroll
                for (int t4 = 0; t4 < 8; ++t4) {
                    float v0 = Vs[k * NB + t4 * 4 + 0][cc];
                    float v1 = Vs[k * NB + t4 * 4 + 1][cc];
                    float v2 = Vs[k * NB + t4 * 4 + 2][cc];
                    float v3 = Vs[k * NB + t4 * 4 + 3][cc];
                    #pragma unroll
                    for (int r4 = 0; r4 < 4; ++r4) {
                        float4 u4 = *(const float4*)&Us[b][q * 4 + r4][t4 * 4];
                        acc[r4] += u4.x * v0 + u4.y * v1 + u4.z * v2 + u4.w * v3;
                    }
                }
            }
            __syncthreads();
        }

        #pragma unroll
        for (int r4 = 0; r4 < 4; ++r4) Ts[q * 4 + r4][cc] = acc[r4];
        {
            const float* din = g_Dinv + ((size_t)g * 16 + i) * NB * NB;
            const int rr = tid >> 3, t4 = tid & 7;
            *(float4*)&Us[0][rr][t4 * 4] = *(const float4*)&din[rr * NB + t4 * 4];
        }
        __syncthreads();

        float acc2[4];
        #pragma unroll
        for (int r4 = 0; r4 < 4; ++r4) acc2[r4] = 0.f;
        #pragma unroll
        for (int t4 = 0; t4 < 8; ++t4) {
            float v0 = Ts[t4 * 4 + 0][cc];
            float v1 = Ts[t4 * 4 + 1][cc];
            float v2 = Ts[t4 * 4 + 2][cc];
            float v3 = Ts[t4 * 4 + 3][cc];
            #pragma unroll
            for (int r4 = 0; r4 < 4; ++r4) {
                float4 u4 = *(const float4*)&Us[0][q * 4 + r4][t4 * 4];
                acc2[r4] += u4.x * v0 + u4.y * v1 + u4.z * v2 + u4.w * v3;
            }
        }
        #pragma unroll
        for (int r4 = 0; r4 < 4; ++r4) Vs[i * NB + q * 4 + r4][cc] = -acc2[r4];
        __syncthreads();
    }

    {
        __half* Whi = g_Wthi + (size_t)g * DD2;
        __half* Wlo = g_Wtlo + (size_t)g * DD2;
        const int kmax  = (j + 1) * NB;
        const int kfill = 128 * ((j >> 2) + 1);
        for (int nl = q; nl < NB; nl += 8) {
            const size_t nbase = (size_t)(j * NB + nl) * DD;
            for (int k = cc; k < kmax; k += 32) {
                float f = Vs[k][nl];
                __half h = __float2half(f);
                __half l = __float2half(f - __half2float(h));
                Whi[nbase + k] = h;
                Wlo[nbase + k] = l;
            }
            for (int k = kmax + cc; k < kfill; k += 32) {
                Whi[nbase + k] = __float2half(0.f);
                Wlo[nbase + k] = __float2half(0.f);
            }
        }
    }

    {
        const float* mu = mus + (size_t)g * DD;
        float s = 0.f;
        for (int row = q; row < (j + 1) * NB; row += 8)
            s += mu[row] * Vs[row][cc];
        __syncthreads();
        Ts[q][cc] = s;
        __syncthreads();
        if (q == 0) {
            float tot = 0.f;
            #pragma unroll
            for (int w8 = 0; w8 < 8; ++w8) tot += Ts[w8][cc];
            g_u[(size_t)g * DD + j * NB + cc] = tot;
        }
    }
}

// ---------------------------------------------------------------------------
// Kernel 4: fp16 2-product GEMM via mma.sync + fused dist epilogue.
// v4: k-stage = 32 (two k16 sub-iterations per barrier round), 3-stage ring.
// Halves the barrier count vs v3. Per-warp triangular stage bound:
// s < nt*4 + wn + 1 (skipped regions are trinv's exact zeros).
// smem/stage: A = 128x40 halfs, B = 128x72 halfs ([hi32|lo32|pad8]).
// ---------------------------------------------------------------------------
#define PITCH_A 40
#define PITCH_B 72
#define A_STAGE (128 * PITCH_A)              // halfs
#define B_STAGE (128 * PITCH_B)
#define MMA_SMEM ((3 * (A_STAGE + B_STAGE)) * 2 + 512 * 4 + 128 * 4 * 4)

__global__ __launch_bounds__(256, 2)
void mma_dist_kernel()
{
    extern __shared__ char smraw[];
    __half* As = (__half*)smraw;                               // [3][128][PITCH_A]
    __half* Bs = (__half*)(smraw + 3 * A_STAGE * 2);           // [3][128][PITCH_B]
    float* sU  = (float*)(smraw + 3 * (A_STAGE + B_STAGE) * 2);
    float (*red)[4] = (float(*)[4])(smraw + 3 * (A_STAGE + B_STAGE) * 2 + 512 * 4);

    const int tid  = threadIdx.x;
    const int lane = tid & 31;
    const int wid  = tid >> 5;
    const int wm   = wid & 1;
    const int wn   = wid >> 1;
    const int g    = blockIdx.y;
    const int b0   = blockIdx.x * 128;

    for (int c = tid; c < 512; c += 256) sU[c] = g_u[(size_t)g * DD + c];

    const __half* Xh = g_Xh + (size_t)b0 * DD;
    const __half* Wh = g_Wthi + (size_t)g * DD2;
    const __half* Wl = g_Wtlo + (size_t)g * DD2;

    const uint32_t aS = (uint32_t)__cvta_generic_to_shared(As);
    const uint32_t bS = (uint32_t)__cvta_generic_to_shared(Bs);
    const uint32_t BUFA = A_STAGE * 2;       // bytes per stage
    const uint32_t BUFB = B_STAGE * 2;

    const int lrow = tid >> 1;               // 0..127
    const int hsel = tid & 1;                // 16-half chunk select
    const int brow = ((lane >> 4) << 3) + (lane & 7);
    const int bcol = ((lane >> 3) & 1) * 8;

    float distacc[8];
    #pragma unroll
    for (int i = 0; i < 8; ++i) distacc[i] = 0.f;

    __syncthreads();   // sU visible

    for (int nt = 0; nt < 4; ++nt) {
        const int n0 = nt * 128;
        const int nsteps = (nt + 1) * 4;       // k32 stages, kend = n0+128
        const int sbound = nt * 4 + wn + 1;    // triangular per-warp stage bound

        float acc[4][4][4];
        #pragma unroll
        for (int mt = 0; mt < 4; ++mt)
            #pragma unroll
            for (int jc = 0; jc < 4; ++jc)
                #pragma unroll
                for (int e = 0; e < 4; ++e) acc[mt][jc][e] = 0.f;

        // stage loader: 6 cp16/thread (A: 2, B hi: 2, B lo: 2)
        #define ISSUE_STAGE(ps)  do {                                           \
            const int _k0 = (ps) * 32;                                          \
            const uint32_t _bf = (uint32_t)((ps) % 3);                          \
            const uint32_t _ar = aS + _bf * BUFA + lrow * (PITCH_A * 2);        \
            const __half* _xh = Xh + (size_t)lrow * DD + _k0 + hsel * 16;       \
            cp16(_ar + hsel * 32,      _xh);                                    \
            cp16(_ar + hsel * 32 + 16, _xh + 8);                                \
            const uint32_t _br = bS + _bf * BUFB + lrow * (PITCH_B * 2);        \
            const __half* _wh = Wh + (size_t)(n0 + lrow) * DD + _k0 + hsel * 16;\
            const __half* _wl = Wl + (size_t)(n0 + lrow) * DD + _k0 + hsel * 16;\
            cp16(_br + hsel * 32,           _wh);                               \
            cp16(_br + hsel * 32 + 16,      _wh + 8);                           \
            cp16(_br + 64 + hsel * 32,      _wl);                               \
            cp16(_br + 64 + hsel * 32 + 16, _wl + 8);                           \
            asm volatile("cp.async.commit_group;");                             \
        } while (0)

        // prologue: issue stages 0 and 1
        ISSUE_STAGE(0);
        if (1 < nsteps) ISSUE_STAGE(1);

        for (int s = 0; s < nsteps; ++s) {
            if (s + 1 < nsteps)
                asm volatile("cp.async.wait_group 1;");
            else
                asm volatile("cp.async.wait_group 0;");
            __syncthreads();

            if (s < sbound) {
                const uint32_t cur = (uint32_t)(s % 3);
                #pragma unroll
                for (int kk = 0; kk < 2; ++kk) {
                    uint32_t ah[4][4];
                    #pragma unroll
                    for (int mt = 0; mt < 4; ++mt) {
                        const uint32_t ad = aS + cur * BUFA
                            + (uint32_t)((wm * 64 + mt * 16 + (lane & 15)) * (PITCH_A * 2))
                            + (uint32_t)(kk * 32 + (lane >> 4) * 16);
                        ldmx4(ah[mt], ad);
                    }
                    #pragma unroll
                    for (int nb = 0; nb < 2; ++nb) {
                        uint32_t bh[4], bl[4];
                        const uint32_t bd = bS + cur * BUFB
                            + (uint32_t)((wn * 32 + nb * 16 + brow) * (PITCH_B * 2))
                            + (uint32_t)(kk * 32 + bcol * 2);
                        ldmx4(bh, bd);
                        ldmx4(bl, bd + 64);
                        #pragma unroll
                        for (int mt = 0; mt < 4; ++mt) {
                            #pragma unroll
                            for (int h = 0; h < 2; ++h) {
                                float* d = acc[mt][nb * 2 + h];
                                mma16816h(d, ah[mt], &bh[h * 2]);
                                mma16816h(d, ah[mt], &bl[h * 2]);
                            }
                        }
                    }
                }
            }

            if (s + 2 < nsteps) ISSUE_STAGE(s + 2);
        }
        #undef ISSUE_STAGE

        // fold (z-u)^2
        #pragma unroll
        for (int mt = 0; mt < 4; ++mt)
            #pragma unroll
            for (int jc = 0; jc < 4; ++jc) {
                const int coln = n0 + wn * 32 + (jc >> 1) * 16 + (jc & 1) * 8 + (lane & 3) * 2;
                const float u0 = sU[coln], u1 = sU[coln + 1];
                float z0 = acc[mt][jc][0] - u0, z1 = acc[mt][jc][1] - u1;
                float z2 = acc[mt][jc][2] - u0, z3 = acc[mt][jc][3] - u1;
                distacc[mt * 2 + 0] += z0 * z0 + z1 * z1;
                distacc[mt * 2 + 1] += z2 * z2 + z3 * z3;
            }
        __syncthreads();   // buffer recycle across nt boundary
    }

    #pragma unroll
    for (int i = 0; i < 8; ++i) {
        distacc[i] += __shfl_xor_sync(0xffffffff, distacc[i], 1);
        distacc[i] += __shfl_xor_sync(0xffffffff, distacc[i], 2);
    }
    if ((lane & 3) == 0) {
        const int r = lane >> 2;
        #pragma unroll
        for (int mt = 0; mt < 4; ++mt) {
            red[wm * 64 + mt * 16 + r][wn]     = distacc[mt * 2 + 0];
            red[wm * 64 + mt * 16 + r + 8][wn] = distacc[mt * 2 + 1];
        }
    }
    __syncthreads();
    if (tid < 128)
        g_dist[(size_t)(b0 + tid) * GG + g] =
            red[tid][0] + red[tid][1] + red[tid][2] + red[tid][3];
}

// ---------------------------------------------------------------------------
// Kernel 5: out = -mean_b( min_g relu(dist[b,g]) ) / 10000
// ---------------------------------------------------------------------------
__global__ __launch_bounds__(256, 1)
void reduce_kernel(float* __restrict__ out)
{
    __shared__ float sh[256];
    float s = 0.f;
    for (int b = threadIdx.x; b < BSZ; b += 256) {
        const float* row = g_dist + (size_t)b * GG;
        float m = fmaxf(row[0], 0.f);
        #pragma unroll 8
        for (int gi = 1; gi < GG; ++gi)
            m = fminf(m, fmaxf(row[gi], 0.f));
        s += m;
    }
    sh[threadIdx.x] = s;
    __syncthreads();
    for (int off = 128; off > 0; off >>= 1) {
        if (threadIdx.x < off) sh[threadIdx.x] += sh[threadIdx.x + off];
        __syncthreads();
    }
    if (threadIdx.x == 0)
        out[0] = -sh[0] / ((float)BSZ * 10000.0f);
}

// ---------------------------------------------------------------------------
extern "C" void kernel_launch(void* const* d_in, const int* in_sizes, int n_in,
                              void* d_out, int out_size)
{
    const float* X    = nullptr;
    const float* mus  = nullptr;
    const float* covs = nullptr;
    for (int i = 0; i < n_in; ++i) {
        if      (in_sizes[i] == BSZ * DD)      X    = (const float*)d_in[i];
        else if (in_sizes[i] == GG * DD)       mus  = (const float*)d_in[i];
        else if (in_sizes[i] == GG * DD * DD)  covs = (const float*)d_in[i];
    }

    static bool attr_done = false;
    if (!attr_done) {
        cudaFuncSetAttribute(trinv_col_kernel,
                             cudaFuncAttributeMaxDynamicSharedMemorySize, T2_SMEM);
        cudaFuncSetAttribute(chol_fused,
                             cudaFuncAttributeMaxDynamicSharedMemorySize, CHOL_SMEM);
        cudaFuncSetAttribute(mma_dist_kernel,
                             cudaFuncAttributeMaxDynamicSharedMemorySize, MMA_SMEM);
        attr_done = true;
    }

    chol_fused<<<GG * 2, 512, CHOL_SMEM>>>(covs);
    diaginv_split_kernel<<<dim3(GG, 4), 128>>>(X);
    trinv_col_kernel<<<dim3(GG, 16), 256, T2_SMEM>>>(mus);
    mma_dist_kernel<<<dim3(BSZ / 128, GG), 256, MMA_SMEM>>>();
    reduce_kernel<<<1, 256>>>((float*)d_out);
}

// round 17
// speedup vs baseline: 1.1201x; 1.0560x over previous
#include <cuda_runtime.h>
#include <cuda_fp16.h>
#include <math.h>
#include <stdint.h>

// Problem sizes (fixed by the reference)
#define BSZ 2048
#define GG  64
#define DD  512
#define DD2 (DD * DD)
#define NB  32
#define PNL 64

// ---------------------------------------------------------------------------
// Scratch (device globals)
// ---------------------------------------------------------------------------
__device__ __align__(16) float g_L[GG * DD2];
__device__ __align__(16) float g_Dinv[GG * 16 * NB * NB];
__device__ __align__(16) float g_u[GG * DD];
__device__ __align__(16) float g_dist[BSZ * GG];
__device__ __align__(16) __half g_Xh[BSZ * DD];
__device__ __align__(16) __half g_Wthi[GG * DD2];
__device__ __align__(16) __half g_Wtlo[GG * DD2];

#define CLUSTER_SYNC() do { \
    asm volatile("barrier.cluster.arrive.aligned;" ::: "memory"); \
    asm volatile("barrier.cluster.wait.aligned;"   ::: "memory"); \
} while (0)

// ---------------------------------------------------------------------------
// mma.sync / cp.async helpers
// ---------------------------------------------------------------------------
__device__ __forceinline__ void ldmx4(uint32_t* r, uint32_t addr) {
    asm volatile("ldmatrix.sync.aligned.m8n8.x4.shared.b16 {%0,%1,%2,%3}, [%4];"
                 : "=r"(r[0]), "=r"(r[1]), "=r"(r[2]), "=r"(r[3]) : "r"(addr));
}
__device__ __forceinline__ void mma16816h(float* d, const uint32_t* a, const uint32_t* b) {
    asm volatile(
        "mma.sync.aligned.m16n8k16.row.col.f32.f16.f16.f32 "
        "{%0,%1,%2,%3}, {%4,%5,%6,%7}, {%8,%9}, {%0,%1,%2,%3};"
        : "+f"(d[0]), "+f"(d[1]), "+f"(d[2]), "+f"(d[3])
        : "r"(a[0]), "r"(a[1]), "r"(a[2]), "r"(a[3]), "r"(b[0]), "r"(b[1]));
}
__device__ __forceinline__ void cp16(uint32_t s, const void* g) {
    asm volatile("cp.async.ca.shared.global [%0], [%1], 16;" :: "r"(s), "l"(g));
}

// ---------------------------------------------------------------------------
// Warp-level 32x32 Cholesky in REGISTERS (lane = row, shfl column broadcast).
// ---------------------------------------------------------------------------
__device__ __forceinline__ void warp_chol32(float (*s)[PNL + 1], int roff, int coff,
                                            float* rdiag)
{
    const int lane = threadIdx.x;
    float x[32];
    #pragma unroll
    for (int j = 0; j < 32; ++j) x[j] = s[roff + lane][coff + j];

    float myrs = 0.f;
    #pragma unroll
    for (int k = 0; k < 32; ++k) {
        float dval = __shfl_sync(0xffffffffu, x[k], k);
        float rs = rsqrtf(dval);
        if (lane == k) { x[k] = dval * rs; myrs = rs; }
        float lik = (lane > k) ? x[k] * rs : 0.f;
        if (lane > k) x[k] = lik;
        #pragma unroll
        for (int j = k + 1; j < 32; ++j) {
            float ljk = __shfl_sync(0xffffffffu, lik, j);
            x[j] -= lik * ljk;
        }
    }
    #pragma unroll
    for (int j = 0; j < 32; ++j) s[roff + lane][coff + j] = x[j];
    rdiag[roff + lane] = myrs;
}

// ---------------------------------------------------------------------------
// Kernel 1: fused blocked Cholesky, NB=64 panels, cluster of 2 CTAs per g,
// 512 threads. v5: SYRK trailing update on TENSOR CORES — each 64x64x64 tile
// C -= P P^T done via fp16 hi/lo split (hh+hl+lh, fp32 accum, ~22-bit
// precision; cov cond ~5 so factor error ~1e-6). P staged fp32 k-major
// (cp.async), converted+transposed to fp16 [row][k] tiles (pitch 72 halfs,
// ldmatrix conflict-free). Same fp16 tile serves both A and B (symmetry).
// smem (floats): s11 4160 | rdiag 64 | Pi 4352 | Pj0 4352 | Pj1 4352 |
//               PiH/PiL/PjH/PjL 4x4608 halfs = 9216 floats   -> 105,984 B
// ---------------------------------------------------------------------------
#define CHOL_SMEM (26496 * 4)

__global__ __launch_bounds__(512) __cluster_dims__(2, 1, 1)
void chol_fused(const float* __restrict__ covs)
{
    extern __shared__ float smc[];
    float (*s11)[PNL + 1] = (float(*)[PNL + 1])smc;          // [64][65]
    float* rdiag          = smc + 4160;
    float (*Pi)[68]       = (float(*)[68])(smc + 4224);
    float (*Pj0)[68]      = (float(*)[68])(smc + 8576);
    float (*Pj1)[68]      = (float(*)[68])(smc + 12928);
    __half* PiH = (__half*)(smc + 17280);
    __half* PiL = PiH + 4608;
    __half* PjH = PiH + 9216;
    __half* PjL = PiH + 13824;

    const int g = blockIdx.x >> 1;
    unsigned crank;
    asm("mov.u32 %0, %%cluster_ctarank;" : "=r"(crank));
    float* a = g_L + (size_t)g * DD2;
    const float* cv = covs + (size_t)g * DD2;
    const int tid  = threadIdx.x;
    const int lane = tid & 31;
    const int wid  = tid >> 5;          // 0..15
    const int wm   = wid & 3;           // m16 band
    const int wn   = wid >> 2;          // n16 band
    const int brow = ((lane >> 4) << 3) + (lane & 7);
    const int bcol = ((lane >> 3) & 1) * 8;

    const uint32_t sPi  = (uint32_t)__cvta_generic_to_shared(&Pi[0][0]);
    const uint32_t sPj0 = (uint32_t)__cvta_generic_to_shared(&Pj0[0][0]);
    const uint32_t sPiH = (uint32_t)__cvta_generic_to_shared(PiH);
    const uint32_t sPjH = (uint32_t)__cvta_generic_to_shared(PjH);

    for (int p = 0; p < DD / PNL; ++p) {
        const int base = p * PNL;
        const int r = DD - base - PNL;
        const float* src = (p == 0) ? cv : a;

        // ---- load 64x64 diag block
        for (int q = tid; q < PNL * PNL; q += 512) {
            int i = q & 63, j = q >> 6;
            s11[i][j] = src[(size_t)(base + j) * DD + (base + i)];
        }
        __syncthreads();

        // ---- hierarchical diag factorization (reg-shfl)
        if (tid < 32) warp_chol32(s11, 0, 0, rdiag);
        __syncthreads();

        if (tid < 32) {
            const int row = 32 + tid;
            float x[32];
            #pragma unroll
            for (int j = 0; j < 32; ++j) x[j] = s11[row][j];
            #pragma unroll
            for (int j = 0; j < 32; ++j) {
                float s = x[j];
                #pragma unroll
                for (int k = 0; k < j; ++k)
                    s -= x[k] * s11[j][k];
                x[j] = s * rdiag[j];
            }
            #pragma unroll
            for (int j = 0; j < 32; ++j) s11[row][j] = x[j];
        }
        __syncthreads();

        #pragma unroll
        for (int e = 0; e < 2; ++e) {
            const int idx = tid + e * 512;
            const int i2 = 32 + (idx >> 5);
            const int j2 = 32 + (idx & 31);
            float s = 0.f;
            #pragma unroll
            for (int k = 0; k < 32; ++k)
                s += s11[i2][k] * s11[j2][k];
            s11[i2][j2] -= s;
        }
        __syncthreads();

        if (tid < 32) warp_chol32(s11, 32, 32, rdiag);
        __syncthreads();

        if (crank == 0) {
            for (int q = tid; q < PNL * PNL; q += 512) {
                int i = q & 63, j = q >> 6;
                if (i >= j) a[(size_t)(base + j) * DD + (base + i)] = s11[i][j];
            }
        }

        // ---- panel solve: my half of the rows, 1 reg-resident row/thread
        if (r > 0) {
            const int chunk = r >> 1;
            const int row = (int)crank * chunk + tid;
            if (row < r && tid < chunk) {
                const int gr = base + PNL + row;
                float x[PNL];
                #pragma unroll
                for (int j = 0; j < PNL; ++j)
                    x[j] = src[(size_t)(base + j) * DD + gr];
                #pragma unroll
                for (int j = 0; j < PNL; ++j) {
                    float s = x[j];
                    #pragma unroll
                    for (int k = 0; k < j; ++k)
                        s -= x[k] * s11[j][k];
                    x[j] = s * rdiag[j];
                }
                #pragma unroll
                for (int j = 0; j < PNL; ++j)
                    a[(size_t)(base + j) * DD + gr] = x[j];
            }
        }
        CLUSTER_SYNC();

        // ---- SYRK trailing update (tensor cores), 64x64 tiles
        if (r > 0) {
            const int m = r >> 6;
            for (int ti = (int)crank; ti < m; ti += 2) {
                const int gi = ti * 64;

                // stage Pi fp32 (k-major) + Pj0 if off-diag tiles exist
                #pragma unroll
                for (int e = 0; e < 2; ++e) {
                    const int f = tid * 2 + e;
                    const int col = f >> 4, r4 = f & 15;
                    cp16(sPi + (uint32_t)((col * 68 + r4 * 4) * 4),
                         a + (size_t)(base + col) * DD + base + PNL + gi + r4 * 4);
                }
                if (ti > 0) {
                    #pragma unroll
                    for (int e = 0; e < 2; ++e) {
                        const int f = tid * 2 + e;
                        const int col = f >> 4, r4 = f & 15;
                        cp16(sPj0 + (uint32_t)((col * 68 + r4 * 4) * 4),
                             a + (size_t)(base + col) * DD + base + PNL + r4 * 4);
                    }
                }
                asm volatile("cp.async.commit_group;");
                asm volatile("cp.async.wait_group 0;");
                __syncthreads();

                // convert+transpose Pi -> PiH/PiL ([row][k], pitch 72)
                #pragma unroll
                for (int e = 0; e < 8; ++e) {
                    const int idx = tid + e * 512;
                    const int row = idx >> 6, k = idx & 63;
                    float f = Pi[k][row];
                    __half h = __float2half(f);
                    PiH[row * 72 + k] = h;
                    PiL[row * 72 + k] = __float2half(f - __half2float(h));
                }
                __syncthreads();

                for (int tj = 0; tj <= ti; ++tj) {
                    const bool diag = (tj == ti);
                    const int gj = tj * 64;

                    // prefetch next fp32 Pj
                    if (tj + 1 < ti) {
                        const int gjn = (tj + 1) * 64;
                        const uint32_t dstb = sPj0 + (uint32_t)(((tj + 1) & 1) ? 4352 * 4 : 0);
                        #pragma unroll
                        for (int e = 0; e < 2; ++e) {
                            const int f = tid * 2 + e;
                            const int col = f >> 4, r4 = f & 15;
                            cp16(dstb + (uint32_t)((col * 68 + r4 * 4) * 4),
                                 a + (size_t)(base + col) * DD + base + PNL + gjn + r4 * 4);
                        }
                        asm volatile("cp.async.commit_group;");
                    }

                    // convert Pj (arrival + prior readers covered by last sync)
                    if (!diag) {
                        const float (*PJ)[68] = (tj & 1) ? Pj1 : Pj0;
                        #pragma unroll
                        for (int e = 0; e < 8; ++e) {
                            const int idx = tid + e * 512;
                            const int row = idx >> 6, k = idx & 63;
                            float f = PJ[k][row];
                            __half h = __float2half(f);
                            PjH[row * 72 + k] = h;
                            PjL[row * 72 + k] = __float2half(f - __half2float(h));
                        }
                        __syncthreads();
                    }

                    const uint32_t bHb = diag ? sPiH : sPjH;

                    float acc[2][4];
                    #pragma unroll
                    for (int h = 0; h < 2; ++h)
                        #pragma unroll
                        for (int e = 0; e < 4; ++e) acc[h][e] = 0.f;

                    #pragma unroll
                    for (int kk = 0; kk < 4; ++kk) {
                        uint32_t ah[4], al[4], bh[4], bl[4];
                        const uint32_t aAddr = sPiH
                            + (uint32_t)((wm * 16 + (lane & 15)) * 144 + kk * 32
                                         + (lane >> 4) * 16);
                        ldmx4(ah, aAddr);
                        ldmx4(al, aAddr + 9216);          // PiL offset
                        const uint32_t bAddr = bHb
                            + (uint32_t)((wn * 16 + brow) * 144 + kk * 32 + bcol * 2);
                        ldmx4(bh, bAddr);
                        ldmx4(bl, bAddr + 9216);          // lo tile offset
                        #pragma unroll
                        for (int h = 0; h < 2; ++h) {
                            float* d = acc[h];
                            mma16816h(d, ah, &bh[h * 2]);
                            mma16816h(d, ah, &bl[h * 2]);
                            mma16816h(d, al, &bh[h * 2]);
                        }
                    }

                    // RMW epilogue (standard fragment layout; tiles are full)
                    {
                        const int rbase = base + PNL + gi + wm * 16 + (lane >> 2);
                        #pragma unroll
                        for (int h = 0; h < 2; ++h) {
                            const int c0 = gj + wn * 16 + h * 8 + (lane & 3) * 2;
                            const size_t off0 = (size_t)(base + PNL + c0) * DD + rbase;
                            const size_t off1 = off0 + DD;
                            a[off0]     = src[off0]     - acc[h][0];
                            a[off1]     = src[off1]     - acc[h][1];
                            a[off0 + 8] = src[off0 + 8] - acc[h][2];
                            a[off1 + 8] = src[off1 + 8] - acc[h][3];
                        }
                    }

                    if (tj + 1 < ti) {
                        asm volatile("cp.async.wait_group 0;");
                        __syncthreads();
                    }
                }
            }
        }
        CLUSTER_SYNC();
    }
}

// ---------------------------------------------------------------------------
// Kernel 2a: diag-block inverse + fused X->fp16 conversion (unchanged).
// ---------------------------------------------------------------------------
__global__ __launch_bounds__(128, 8)
void diaginv_split_kernel(const float* __restrict__ X)
{
    __shared__ float su[4][NB][NB + 1];
    __shared__ float sx[4][NB][NB + 1];

    const int g = blockIdx.x;
    const int w = threadIdx.x >> 5;
    const int d = blockIdx.y * 4 + w;
    const int cc = threadIdx.x & 31;
    const float* U = g_L + (size_t)g * DD2;
    const int b0 = d * NB;

    {
        const int blk = blockIdx.y * GG + blockIdx.x;
        const int base = blk * 1024 + threadIdx.x;
        #pragma unroll
        for (int e = 0; e < 8; ++e) {
            const int i = base + e * 128;
            float4 v = ((const float4*)X)[i];
            __half h[4] = {__float2half(v.x), __float2half(v.y),
                           __float2half(v.z), __float2half(v.w)};
            ((uint2*)g_Xh)[i] = *(uint2*)h;
        }
    }

    for (int rr = 0; rr < NB; ++rr)
        su[w][rr][cc] = U[(size_t)(b0 + rr) * DD + (b0 + cc)];
    __syncwarp();

    for (int t = cc; t >= 0; --t) {
        float s = (t == cc) ? 1.f : 0.f;
        for (int ss = t + 1; ss <= cc; ++ss)
            s -= su[w][t][ss] * sx[w][ss][cc];
        sx[w][t][cc] = s / su[w][t][t];
    }
    __syncwarp();

    float* dst = g_Dinv + ((size_t)g * 16 + d) * NB * NB;
    for (int t = 0; t < NB; ++t)
        dst[t * NB + cc] = (t <= cc) ? sx[w][t][cc] : 0.f;
}

// ---------------------------------------------------------------------------
// Kernel 2b: blocked triangular inverse (R13 measured-best version).
// ---------------------------------------------------------------------------
#define T2_SMEM ((512*36 + 4*32*36 + 32*33) * 4)

__global__ __launch_bounds__(256)
void trinv_col_kernel(const float* __restrict__ mus)
{
    extern __shared__ float sm2[];
    float (*Vs)[36] = (float(*)[36])sm2;
    float (*Us)[32][36] = (float(*)[32][36])(sm2 + 512 * 36);
    float (*Ts)[33] = (float(*)[33])(sm2 + 512 * 36 + 4 * 32 * 36);

    const int g = blockIdx.x;
    const int j = 15 - blockIdx.y;
    const float* U = g_L + (size_t)g * DD2;
    const int tid = threadIdx.x;
    const int cc  = tid & 31;
    const int q   = tid >> 5;

    {
        const float* din = g_Dinv + ((size_t)g * 16 + j) * NB * NB;
        #pragma unroll
        for (int t4 = 0; t4 < 4; ++t4) {
            int t = q * 4 + t4;
            Vs[j * NB + t][cc] = din[t * NB + cc];
        }
    }
    __syncthreads();

    for (int i = j - 1; i >= 0; --i) {
        float acc[4];
        #pragma unroll
        for (int r4 = 0; r4 < 4; ++r4) acc[r4] = 0.f;

        for (int kc = i + 1; kc <= j; kc += 4) {
            const int nk = (j - kc + 1 < 4) ? (j - kc + 1) : 4;
            for (int b = 0; b < nk; ++b) {
                const float* ub = U + (size_t)(i * NB) * DD + (kc + b) * NB;
                const int rr = tid >> 3, t4 = tid & 7;
                *(float4*)&Us[b][rr][t4 * 4] = *(const float4*)&ub[(size_t)rr * DD + t4 * 4];
            }
            __syncthreads();
            for (int b = 0; b < nk; ++b) {
                const int k = kc + b;
                #pragma unroll
                for (int t4 = 0; t4 < 8; ++t4) {
                    float v0 = Vs[k * NB + t4 * 4 + 0][cc];
                    float v1 = Vs[k * NB + t4 * 4 + 1][cc];
                    float v2 = Vs[k * NB + t4 * 4 + 2][cc];
                    float v3 = Vs[k * NB + t4 * 4 + 3][cc];
                    #pragma unroll
                    for (int r4 = 0; r4 < 4; ++r4) {
                        float4 u4 = *(const float4*)&Us[b][q * 4 + r4][t4 * 4];
                        acc[r4] += u4.x * v0 + u4.y * v1 + u4.z * v2 + u4.w * v3;
                    }
                }
            }
            __syncthreads();
        }

        #pragma unroll
        for (int r4 = 0; r4 < 4; ++r4) Ts[q * 4 + r4][cc] = acc[r4];
        {
            const float* din = g_Dinv + ((size_t)g * 16 + i) * NB * NB;
            const int rr = tid >> 3, t4 = tid & 7;
            *(float4*)&Us[0][rr][t4 * 4] = *(const float4*)&din[rr * NB + t4 * 4];
        }
        __syncthreads();

        float acc2[4];
        #pragma unroll
        for (int r4 = 0; r4 < 4; ++r4) acc2[r4] = 0.f;
        #pragma unroll
        for (int t4 = 0; t4 < 8; ++t4) {
            float v0 = Ts[t4 * 4 + 0][cc];
            float v1 = Ts[t4 * 4 + 1][cc];
            float v2 = Ts[t4 * 4 + 2][cc];
            float v3 = Ts[t4 * 4 + 3][cc];
            #pragma unroll
            for (int r4 = 0; r4 < 4; ++r4) {
                float4 u4 = *(const float4*)&Us[0][q * 4 + r4][t4 * 4];
                acc2[r4] += u4.x * v0 + u4.y * v1 + u4.z * v2 + u4.w * v3;
            }
        }
        #pragma unroll
        for (int r4 = 0; r4 < 4; ++r4) Vs[i * NB + q * 4 + r4][cc] = -acc2[r4];
        __syncthreads();
    }

    {
        __half* Whi = g_Wthi + (size_t)g * DD2;
        __half* Wlo = g_Wtlo + (size_t)g * DD2;
        const int kmax  = (j + 1) * NB;
        const int kfill = 128 * ((j >> 2) + 1);
        for (int nl = q; nl < NB; nl += 8) {
            const size_t nbase = (size_t)(j * NB + nl) * DD;
            for (int k = cc; k < kmax; k += 32) {
                float f = Vs[k][nl];
                __half h = __float2half(f);
                __half l = __float2half(f - __half2float(h));
                Whi[nbase + k] = h;
                Wlo[nbase + k] = l;
            }
            for (int k = kmax + cc; k < kfill; k += 32) {
                Whi[nbase + k] = __float2half(0.f);
                Wlo[nbase + k] = __float2half(0.f);
            }
        }
    }

    {
        const float* mu = mus + (size_t)g * DD;
        float s = 0.f;
        for (int row = q; row < (j + 1) * NB; row += 8)
            s += mu[row] * Vs[row][cc];
        __syncthreads();
        Ts[q][cc] = s;
        __syncthreads();
        if (q == 0) {
            float tot = 0.f;
            #pragma unroll
            for (int w8 = 0; w8 < 8; ++w8) tot += Ts[w8][cc];
            g_u[(size_t)g * DD + j * NB + cc] = tot;
        }
    }
}

// ---------------------------------------------------------------------------
// Kernel 4: fp16 2-product GEMM via mma.sync + fused dist epilogue.
// (R16 v4, measured 225us — frozen)
// ---------------------------------------------------------------------------
#define PITCH_A 40
#define PITCH_B 72
#define A_STAGE (128 * PITCH_A)
#define B_STAGE (128 * PITCH_B)
#define MMA_SMEM ((3 * (A_STAGE + B_STAGE)) * 2 + 512 * 4 + 128 * 4 * 4)

__global__ __launch_bounds__(256, 2)
void mma_dist_kernel()
{
    extern __shared__ char smraw[];
    __half* As = (__half*)smraw;
    __half* Bs = (__half*)(smraw + 3 * A_STAGE * 2);
    float* sU  = (float*)(smraw + 3 * (A_STAGE + B_STAGE) * 2);
    float (*red)[4] = (float(*)[4])(smraw + 3 * (A_STAGE + B_STAGE) * 2 + 512 * 4);

    const int tid  = threadIdx.x;
    const int lane = tid & 31;
    const int wid  = tid >> 5;
    const int wm   = wid & 1;
    const int wn   = wid >> 1;
    const int g    = blockIdx.y;
    const int b0   = blockIdx.x * 128;

    for (int c = tid; c < 512; c += 256) sU[c] = g_u[(size_t)g * DD + c];

    const __half* Xh = g_Xh + (size_t)b0 * DD;
    const __half* Wh = g_Wthi + (size_t)g * DD2;
    const __half* Wl = g_Wtlo + (size_t)g * DD2;

    const uint32_t aS = (uint32_t)__cvta_generic_to_shared(As);
    const uint32_t bS = (uint32_t)__cvta_generic_to_shared(Bs);
    const uint32_t BUFA = A_STAGE * 2;
    const uint32_t BUFB = B_STAGE * 2;

    const int lrow = tid >> 1;
    const int hsel = tid & 1;
    const int brow = ((lane >> 4) << 3) + (lane & 7);
    const int bcol = ((lane >> 3) & 1) * 8;

    float distacc[8];
    #pragma unroll
    for (int i = 0; i < 8; ++i) distacc[i] = 0.f;

    __syncthreads();

    for (int nt = 0; nt < 4; ++nt) {
        const int n0 = nt * 128;
        const int nsteps = (nt + 1) * 4;
        const int sbound = nt * 4 + wn + 1;

        float acc[4][4][4];
        #pragma unroll
        for (int mt = 0; mt < 4; ++mt)
            #pragma unroll
            for (int jc = 0; jc < 4; ++jc)
                #pragma unroll
                for (int e = 0; e < 4; ++e) acc[mt][jc][e] = 0.f;

        #define ISSUE_STAGE(ps)  do {                                           \
            const int _k0 = (ps) * 32;                                          \
            const uint32_t _bf = (uint32_t)((ps) % 3);                          \
            const uint32_t _ar = aS + _bf * BUFA + lrow * (PITCH_A * 2);        \
            const __half* _xh = Xh + (size_t)lrow * DD + _k0 + hsel * 16;       \
            cp16(_ar + hsel * 32,      _xh);                                    \
            cp16(_ar + hsel * 32 + 16, _xh + 8);                                \
            const uint32_t _br = bS + _bf * BUFB + lrow * (PITCH_B * 2);        \
            const __half* _wh = Wh + (size_t)(n0 + lrow) * DD + _k0 + hsel * 16;\
            const __half* _wl = Wl + (size_t)(n0 + lrow) * DD + _k0 + hsel * 16;\
            cp16(_br + hsel * 32,           _wh);                               \
            cp16(_br + hsel * 32 + 16,      _wh + 8);                           \
            cp16(_br + 64 + hsel * 32,      _wl);                               \
            cp16(_br + 64 + hsel * 32 + 16, _wl + 8);                           \
            asm volatile("cp.async.commit_group;");                             \
        } while (0)

        ISSUE_STAGE(0);
        if (1 < nsteps) ISSUE_STAGE(1);

        for (int s = 0; s < nsteps; ++s) {
            if (s + 1 < nsteps)
                asm volatile("cp.async.wait_group 1;");
            else
                asm volatile("cp.async.wait_group 0;");
            __syncthreads();

            if (s < sbound) {
                const uint32_t cur = (uint32_t)(s % 3);
                #pragma unroll
                for (int kk = 0; kk < 2; ++kk) {
                    uint32_t ah[4][4];
                    #pragma unroll
                    for (int mt = 0; mt < 4; ++mt) {
                        const uint32_t ad = aS + cur * BUFA
                            + (uint32_t)((wm * 64 + mt * 16 + (lane & 15)) * (PITCH_A * 2))
                            + (uint32_t)(kk * 32 + (lane >> 4) * 16);
                        ldmx4(ah[mt], ad);
                    }
                    #pragma unroll
                    for (int nb = 0; nb < 2; ++nb) {
                        uint32_t bh[4], bl[4];
                        const uint32_t bd = bS + cur * BUFB
                            + (uint32_t)((wn * 32 + nb * 16 + brow) * (PITCH_B * 2))
                            + (uint32_t)(kk * 32 + bcol * 2);
                        ldmx4(bh, bd);
                        ldmx4(bl, bd + 64);
                        #pragma unroll
                        for (int mt = 0; mt < 4; ++mt) {
                            #pragma unroll
                            for (int h = 0; h < 2; ++h) {
                                float* d = acc[mt][nb * 2 + h];
                                mma16816h(d, ah[mt], &bh[h * 2]);
                                mma16816h(d, ah[mt], &bl[h * 2]);
                            }
                        }
                    }
                }
            }

            if (s + 2 < nsteps) ISSUE_STAGE(s + 2);
        }
        #undef ISSUE_STAGE

        #pragma unroll
        for (int mt = 0; mt < 4; ++mt)
            #pragma unroll
            for (int jc = 0; jc < 4; ++jc) {
                const int coln = n0 + wn * 32 + (jc >> 1) * 16 + (jc & 1) * 8 + (lane & 3) * 2;
                const float u0 = sU[coln], u1 = sU[coln + 1];
                float z0 = acc[mt][jc][0] - u0, z1 = acc[mt][jc][1] - u1;
                float z2 = acc[mt][jc][2] - u0, z3 = acc[mt][jc][3] - u1;
                distacc[mt * 2 + 0] += z0 * z0 + z1 * z1;
                distacc[mt * 2 + 1] += z2 * z2 + z3 * z3;
            }
        __syncthreads();
    }

    #pragma unroll
    for (int i = 0; i < 8; ++i) {
        distacc[i] += __shfl_xor_sync(0xffffffff, distacc[i], 1);
        distacc[i] += __shfl_xor_sync(0xffffffff, distacc[i], 2);
    }
    if ((lane & 3) == 0) {
        const int r = lane >> 2;
        #pragma unroll
        for (int mt = 0; mt < 4; ++mt) {
            red[wm * 64 + mt * 16 + r][wn]     = distacc[mt * 2 + 0];
            red[wm * 64 + mt * 16 + r + 8][wn] = distacc[mt * 2 + 1];
        }
    }
    __syncthreads();
    if (tid < 128)
        g_dist[(size_t)(b0 + tid) * GG + g] =
            red[tid][0] + red[tid][1] + red[tid][2] + red[tid][3];
}

// ---------------------------------------------------------------------------
// Kernel 5: out = -mean_b( min_g relu(dist[b,g]) ) / 10000
// ---------------------------------------------------------------------------
__global__ __launch_bounds__(256, 1)
void reduce_kernel(float* __restrict__ out)
{
    __shared__ float sh[256];
    float s = 0.f;
    for (int b = threadIdx.x; b < BSZ; b += 256) {
        const float* row = g_dist + (size_t)b * GG;
        float m = fmaxf(row[0], 0.f);
        #pragma unroll 8
        for (int gi = 1; gi < GG; ++gi)
            m = fminf(m, fmaxf(row[gi], 0.f));
        s += m;
    }
    sh[threadIdx.x] = s;
    __syncthreads();
    for (int off = 128; off > 0; off >>= 1) {
        if (threadIdx.x < off) sh[threadIdx.x] += sh[threadIdx.x + off];
        __syncthreads();
    }
    if (threadIdx.x == 0)
        out[0] = -sh[0] / ((float)BSZ * 10000.0f);
}

// ---------------------------------------------------------------------------
extern "C" void kernel_launch(void* const* d_in, const int* in_sizes, int n_in,
                              void* d_out, int out_size)
{
    const float* X    = nullptr;
    const float* mus  = nullptr;
    const float* covs = nullptr;
    for (int i = 0; i < n_in; ++i) {
        if      (in_sizes[i] == BSZ * DD)      X    = (const float*)d_in[i];
        else if (in_sizes[i] == GG * DD)       mus  = (const float*)d_in[i];
        else if (in_sizes[i] == GG * DD * DD)  covs = (const float*)d_in[i];
    }

    static bool attr_done = false;
    if (!attr_done) {
        cudaFuncSetAttribute(trinv_col_kernel,
                             cudaFuncAttributeMaxDynamicSharedMemorySize, T2_SMEM);
        cudaFuncSetAttribute(chol_fused,
                             cudaFuncAttributeMaxDynamicSharedMemorySize, CHOL_SMEM);
        cudaFuncSetAttribute(mma_dist_kernel,
                             cudaFuncAttributeMaxDynamicSharedMemorySize, MMA_SMEM);
        attr_done = true;
    }

    chol_fused<<<GG * 2, 512, CHOL_SMEM>>>(covs);
    diaginv_split_kernel<<<dim3(GG, 4), 128>>>(X);
    trinv_col_kernel<<<dim3(GG, 16), 256, T2_SMEM>>>(mus);
    mma_dist_kernel<<<dim3(BSZ / 128, GG), 256, MMA_SMEM>>>();
    reduce_kernel<<<1, 256>>>((float*)d_out);
}